// round 10
// baseline (speedup 1.0000x reference)
#include <cuda_runtime.h>
#include <cuda_bf16.h>

typedef unsigned int u32; typedef unsigned long long u64;
#define Mmol 2048
#define Aat 24
#define PIT 272
#define IMG 34816

// EA fragments per (m,d): 8 ks-chunks of 512 u32 [hi mb0|hi mb1|lo mb0|lo mb1]
__device__ u32 g_EAf[(size_t)Mmol*24*4096];
__device__ __align__(16) unsigned char g_Wimg[5][2][32768]; // [nlw,ew1,ew2,nw1,nw2][hi,lo]

__device__ __forceinline__ u32 smaddr(const void* p){
    u32 a; asm("{ .reg .u64 t; cvta.to.shared.u64 t, %1; cvt.u32.u64 %0, t; }" : "=r"(a) : "l"(p)); return a;
}
__device__ __forceinline__ float ssp(float x){
    return fmaxf(x, 0.f) + __logf(1.f + __expf(-fabsf(x))) - 0.6931471805599453f;
}
__device__ __forceinline__ void cpa16(u32 dst, const void* src){
    asm volatile("cp.async.cg.shared.global [%0], [%1], 16;" :: "r"(dst), "l"(src) : "memory");
}
#define CP_COMMIT asm volatile("cp.async.commit_group;" ::: "memory")
#define CP_WAIT0  asm volatile("cp.async.wait_group 0;"  ::: "memory")
__device__ __forceinline__ void ldsm4t(u32* r, u32 a){
    asm volatile("ldmatrix.sync.aligned.m8n8.x4.trans.shared.b16 {%0,%1,%2,%3}, [%4];"
        : "=r"(r[0]),"=r"(r[1]),"=r"(r[2]),"=r"(r[3]) : "r"(a));
}
__device__ __forceinline__ void mma_bf(float* d, const u32* a, u32 b0, u32 b1){
    asm volatile("mma.sync.aligned.m16n8k16.row.col.f32.bf16.bf16.f32 "
        "{%0,%1,%2,%3}, {%4,%5,%6,%7}, {%8,%9}, {%0,%1,%2,%3};"
        : "+f"(d[0]),"+f"(d[1]),"+f"(d[2]),"+f"(d[3])
        : "r"(a[0]),"r"(a[1]),"r"(a[2]),"r"(a[3]),"r"(b0),"r"(b1));
}
__device__ __forceinline__ void sp2(float x, float y, u32& h, u32& l){
    __nv_bfloat162 hb = __floats2bfloat162_rn(x, y);
    __nv_bfloat162 lb = __floats2bfloat162_rn(x - __bfloat162float(hb.x), y - __bfloat162float(hb.y));
    h = *(u32*)&hb; l = *(u32*)&lb;
}

__global__ void k_init(const float* nlw, const float* ew1, const float* ew2,
                       const float* nw1, const float* nw2){
    const float* srcs[5] = {nlw, ew1, ew2, nw1, nw2};
    const float* src = srcs[blockIdx.x];
    int n = threadIdx.x;
    for (int k = 0; k < 128; ++k){
        float v = src[k*128 + n];
        __nv_bfloat16 h = __float2bfloat16_rn(v);
        __nv_bfloat16 l = __float2bfloat16_rn(v - __bfloat162float(h));
        *(__nv_bfloat16*)(g_Wimg[blockIdx.x][0] + k*256 + n*2) = h;
        *(__nv_bfloat16*)(g_Wimg[blockIdx.x][1] + k*256 + n*2) = l;
    }
}

// M=32 x N=128 GEMM, A(fp32, smem, stride 132, rows<24 real) * B(image pair), 3-term.
__device__ __forceinline__ void gemm_sm(const float* abuf, u32 bhi, u32 bli,
                                        int mb, int cg, int lane, u32 loff, float acc[4][4]){
    const int q = lane>>2, cp = lane&3;
    const int r0 = mb*16 + q, r1 = r0 + 8;
    const bool ok1 = (r1 < 24);
    #pragma unroll
    for (int ks=0; ks<8; ++ks){
        int kc = 16*ks + 2*cp;
        float2 v0 = *(const float2*)&abuf[r0*132+kc];
        float2 v1 = ok1 ? *(const float2*)&abuf[r1*132+kc] : make_float2(0.f,0.f);
        float2 v2 = *(const float2*)&abuf[r0*132+kc+8];
        float2 v3 = ok1 ? *(const float2*)&abuf[r1*132+kc+8] : make_float2(0.f,0.f);
        u32 ah[4], al[4];
        sp2(v0.x,v0.y,ah[0],al[0]); sp2(v1.x,v1.y,ah[1],al[1]);
        sp2(v2.x,v2.y,ah[2],al[2]); sp2(v3.x,v3.y,ah[3],al[3]);
        #pragma unroll
        for (int j=0;j<2;++j){
            u32 bh[4],bl[4]; u32 ba = loff + ks*(16*PIT) + (cg*2+j)*32;
            ldsm4t(bh, bhi+ba); ldsm4t(bl, bli+ba);
            mma_bf(acc[2*j],   ah, bh[0], bh[1]);
            mma_bf(acc[2*j],   ah, bl[0], bl[1]);
            mma_bf(acc[2*j],   al, bh[0], bh[1]);
            mma_bf(acc[2*j+1], ah, bh[2], bh[3]);
            mma_bf(acc[2*j+1], ah, bl[2], bl[3]);
            mma_bf(acc[2*j+1], al, bh[2], bh[3]);
        }
    }
}

__global__ void __launch_bounds__(256,1) k_fused(
    const int* __restrict__ charges, const float* __restrict__ coords,
    const float* __restrict__ emb,
    const float* __restrict__ eb1, const float* __restrict__ eb2,
    const float* __restrict__ nb1, const float* __restrict__ nb2,
    const float* __restrict__ gw1, const float* __restrict__ gb1,
    const float* __restrict__ gw2, const float* __restrict__ gb2,
    float* __restrict__ out)
{
    extern __shared__ __align__(16) char sm[];
    char *WAh = sm, *WAl = sm+IMG, *WBh = sm+2*IMG, *WBl = sm+3*IMG;
    float* hs   = (float*)(sm + 4*IMG);   // 24x132
    float* xs   = hs + 24*132;            // 32x132 (rows 24-31 stay zero)
    float* sagg = xs + 32*132;            // 24x132
    float* bb   = sagg + 24*132;          // 512: eb1|eb2|nb1|nb2
    const int tid = threadIdx.x, m = blockIdx.x;
    const int wid = tid>>5, lane = tid&31, q = lane>>2, cp = lane&3;
    const u32 loff = (lane&15)*PIT + (lane>>4)*16;
    const u32 sAh = smaddr(WAh), sAl = smaddr(WAl), sBh = smaddr(WBh), sBl = smaddr(WBl);
    const int mb = wid & 1, cg = wid >> 1;

    for (int i = tid; i < Aat*128; i += 256)
        hs[(i>>7)*132 + (i&127)] = emb[charges[m*Aat + (i>>7)]*128 + (i&127)];
    for (int i = tid; i < 8*132; i += 256) xs[24*132 + i] = 0.f;
    if (tid < 128){ bb[tid]=eb1[tid]; bb[128+tid]=eb2[tid]; bb[256+tid]=nb1[tid]; bb[384+tid]=nb2[tid]; }

    // ---- RBF -> EA fragments (3 d's per warp) ----
    {
        const float* cm = coords + (size_t)m*72;
        for (int i3 = 0; i3 < 3; ++i3){
            int d = wid + 8*i3;
            float ddx=cm[d*3], ddy=cm[d*3+1], ddz=cm[d*3+2];
            float dv[3];
            #pragma unroll
            for (int i=0;i<3;++i){
                int s = q + i*8;
                float ax=cm[s*3]-ddx, ay=cm[s*3+1]-ddy, az=cm[s*3+2]-ddz;
                dv[i] = sqrtf(ax*ax+ay*ay+az*az);
            }
            const float delta = 10.f/127.f, coeff = -0.5f/(delta*delta);
            u32* base = g_EAf + ((size_t)(m*24+d))*4096;
            #pragma unroll
            for (int ks=0; ks<8; ++ks){
                float c0 = (float)(16*ks + 2*cp);
                float v[3][4];
                #pragma unroll
                for (int i=0;i<3;++i)
                    #pragma unroll
                    for (int j=0;j<4;++j){
                        float od = dv[i] - delta*(c0 + (float)((j>>1)*8 + (j&1)));
                        v[i][j] = (fabsf(od) < 1.2f) ? __expf(coeff*od*od) : 0.f;
                    }
                u32 h[4],l[4],h2[4],l2[4];
                sp2(v[0][0],v[0][1],h[0],l[0]);  sp2(v[1][0],v[1][1],h[1],l[1]);
                sp2(v[0][2],v[0][3],h[2],l[2]);  sp2(v[1][2],v[1][3],h[3],l[3]);
                sp2(v[2][0],v[2][1],h2[0],l2[0]); h2[1]=0; l2[1]=0;
                sp2(v[2][2],v[2][3],h2[2],l2[2]); h2[3]=0; l2[3]=0;
                u32* c = base + ks*512;
                *(uint4*)(c + lane*4)       = make_uint4(h[0],h[1],h[2],h[3]);
                *(uint4*)(c + 128 + lane*4) = make_uint4(h2[0],h2[1],h2[2],h2[3]);
                *(uint4*)(c + 256 + lane*4) = make_uint4(l[0],l[1],l[2],l[3]);
                *(uint4*)(c + 384 + lane*4) = make_uint4(l2[0],l2[1],l2[2],l2[3]);
            }
        }
    }

    const float* b1s = bb;
    const float* b2s = bb + 128;

    for (int layer = 0; layer < 4; ++layer){
        // ===== x = h @ nlw =====
        for (int i=tid;i<2048;i+=256){
            int k=i>>4, ch=i&15; u32 dof=k*PIT+ch*16;
            cpa16(sAh+dof, g_Wimg[0][0]+i*16); cpa16(sAl+dof, g_Wimg[0][1]+i*16);
        }
        CP_COMMIT; CP_WAIT0; __syncthreads();
        {
            float acc[4][4];
            #pragma unroll
            for (int i=0;i<4;++i){acc[i][0]=0;acc[i][1]=0;acc[i][2]=0;acc[i][3]=0;}
            gemm_sm(hs, sAh, sAl, mb, cg, lane, loff, acc);
            int r0 = mb*16+q, r1 = r0+8;
            #pragma unroll
            for (int jb=0;jb<4;++jb){
                int c = (cg*2+(jb>>1))*16 + (jb&1)*8 + 2*cp;
                *(float2*)&xs[r0*132+c] = make_float2(acc[jb][0], acc[jb][1]);
                if (r1 < 24) *(float2*)&xs[r1*132+c] = make_float2(acc[jb][2], acc[jb][3]);
            }
        }
        __syncthreads();
        // ===== edge phase =====
        for (int i=tid;i<2048;i+=256){
            int k=i>>4, ch=i&15; u32 dof=k*PIT+ch*16;
            cpa16(sAh+dof, g_Wimg[1][0]+i*16); cpa16(sAl+dof, g_Wimg[1][1]+i*16);
            cpa16(sBh+dof, g_Wimg[2][0]+i*16); cpa16(sBl+dof, g_Wimg[2][1]+i*16);
        }
        CP_COMMIT; CP_WAIT0; __syncthreads();
        for (int pass=0; pass<3; ++pass){
            const int d = pass*8 + wid;
            u32* base = g_EAf + ((size_t)(m*24+d))*4096;

            // ---- GEMM1 in two N-halves, immediate a2 conversion (reg-lean) ----
            u32 a2h[2][8][4], a2l[2][8][4];
            #pragma unroll
            for (int half=0; half<2; ++half){
                float acc1[2][8][4];
                #pragma unroll
                for (int i=0;i<8;++i){
                    acc1[0][i][0]=0;acc1[0][i][1]=0;acc1[0][i][2]=0;acc1[0][i][3]=0;
                    acc1[1][i][0]=0;acc1[1][i][1]=0;acc1[1][i][2]=0;acc1[1][i][3]=0;
                }
                uint4 H0=*(const uint4*)(base+lane*4),     H1=*(const uint4*)(base+128+lane*4);
                uint4 L0=*(const uint4*)(base+256+lane*4), L1=*(const uint4*)(base+384+lane*4);
                #pragma unroll
                for (int ks=0;ks<8;++ks){
                    uint4 nH0,nH1,nL0,nL1;
                    if (ks<7){
                        const u32* nb = base+(ks+1)*512;
                        nH0=*(const uint4*)(nb+lane*4);     nH1=*(const uint4*)(nb+128+lane*4);
                        nL0=*(const uint4*)(nb+256+lane*4); nL1=*(const uint4*)(nb+384+lane*4);
                    }
                    u32 ah0[4]={H0.x,H0.y,H0.z,H0.w}, ah1[4]={H1.x,H1.y,H1.z,H1.w};
                    u32 al0[4]={L0.x,L0.y,L0.z,L0.w}, al1[4]={L1.x,L1.y,L1.z,L1.w};
                    #pragma unroll
                    for (int j=0;j<4;++j){
                        int jj = half*4 + j;
                        u32 bh[4],bl[4]; u32 ba=loff+ks*(16*PIT)+jj*32;
                        ldsm4t(bh,sAh+ba); ldsm4t(bl,sAl+ba);
                        mma_bf(acc1[0][2*j],   ah0,bh[0],bh[1]); mma_bf(acc1[0][2*j],   ah0,bl[0],bl[1]); mma_bf(acc1[0][2*j],   al0,bh[0],bh[1]);
                        mma_bf(acc1[0][2*j+1], ah0,bh[2],bh[3]); mma_bf(acc1[0][2*j+1], ah0,bl[2],bl[3]); mma_bf(acc1[0][2*j+1], al0,bh[2],bh[3]);
                        mma_bf(acc1[1][2*j],   ah1,bh[0],bh[1]); mma_bf(acc1[1][2*j],   ah1,bl[0],bl[1]); mma_bf(acc1[1][2*j],   al1,bh[0],bh[1]);
                        mma_bf(acc1[1][2*j+1], ah1,bh[2],bh[3]); mma_bf(acc1[1][2*j+1], ah1,bl[2],bl[3]); mma_bf(acc1[1][2*j+1], al1,bh[2],bh[3]);
                    }
                    if (ks<7){ H0=nH0; H1=nH1; L0=nL0; L1=nL1; }
                }
                #pragma unroll
                for (int mb2=0;mb2<2;++mb2)
                    #pragma unroll
                    for (int j=0;j<4;++j){
                        int jj = half*4 + j;
                        int c0 = 16*jj + 2*cp;
                        float bA0=b1s[c0], bA1=b1s[c0+1], bB0=b1s[c0+8], bB1=b1s[c0+9];
                        sp2(ssp(acc1[mb2][2*j][0]+bA0),   ssp(acc1[mb2][2*j][1]+bA1),   a2h[mb2][jj][0], a2l[mb2][jj][0]);
                        sp2(ssp(acc1[mb2][2*j][2]+bA0),   ssp(acc1[mb2][2*j][3]+bA1),   a2h[mb2][jj][1], a2l[mb2][jj][1]);
                        sp2(ssp(acc1[mb2][2*j+1][0]+bB0), ssp(acc1[mb2][2*j+1][1]+bB1), a2h[mb2][jj][2], a2l[mb2][jj][2]);
                        sp2(ssp(acc1[mb2][2*j+1][2]+bB0), ssp(acc1[mb2][2*j+1][3]+bB1), a2h[mb2][jj][3], a2l[mb2][jj][3]);
                    }
            }
            // ---- GEMM2 in two N-halves + fused epilogue ----
            #pragma unroll
            for (int hf=0; hf<2; ++hf){
                float acc2[2][8][4];
                #pragma unroll
                for (int i=0;i<8;++i){
                    acc2[0][i][0]=0;acc2[0][i][1]=0;acc2[0][i][2]=0;acc2[0][i][3]=0;
                    acc2[1][i][0]=0;acc2[1][i][1]=0;acc2[1][i][2]=0;acc2[1][i][3]=0;
                }
                #pragma unroll
                for (int ks=0;ks<8;++ks)
                    #pragma unroll
                    for (int j=0;j<4;++j){
                        u32 bh[4],bl[4]; u32 ba=loff+ks*(16*PIT)+(hf*4+j)*32;
                        ldsm4t(bh,sBh+ba); ldsm4t(bl,sBl+ba);
                        #pragma unroll
                        for (int mb2=0;mb2<2;++mb2){
                            mma_bf(acc2[mb2][2*j],   a2h[mb2][ks],bh[0],bh[1]);
                            mma_bf(acc2[mb2][2*j],   a2h[mb2][ks],bl[0],bl[1]);
                            mma_bf(acc2[mb2][2*j],   a2l[mb2][ks],bh[0],bh[1]);
                            mma_bf(acc2[mb2][2*j+1], a2h[mb2][ks],bh[2],bh[3]);
                            mma_bf(acc2[mb2][2*j+1], a2h[mb2][ks],bl[2],bl[3]);
                            mma_bf(acc2[mb2][2*j+1], a2l[mb2][ks],bh[2],bh[3]);
                        }
                    }
                float wag[4][4];
                #pragma unroll
                for (int j=0;j<4;++j){wag[j][0]=0;wag[j][1]=0;wag[j][2]=0;wag[j][3]=0;}
                #pragma unroll
                for (int mb2=0;mb2<2;++mb2){
                    int s0=mb2*16+q, s1=s0+8;
                    bool k0=(s0<24)&&(s0!=d), k1=(s1<24)&&(s1!=d);
                    #pragma unroll
                    for (int j=0;j<4;++j){
                        int cA=hf*64+16*j+2*cp, cB=cA+8;
                        float bA0=b2s[cA],bA1=b2s[cA+1],bB0=b2s[cB],bB1=b2s[cB+1];
                        float v00=(acc2[mb2][2*j][0]+bA0)*xs[s0*132+cA];
                        float v01=(acc2[mb2][2*j][1]+bA1)*xs[s0*132+cA+1];
                        float v10=(acc2[mb2][2*j][2]+bA0)*xs[s1*132+cA];
                        float v11=(acc2[mb2][2*j][3]+bA1)*xs[s1*132+cA+1];
                        float w00=(acc2[mb2][2*j+1][0]+bB0)*xs[s0*132+cB];
                        float w01=(acc2[mb2][2*j+1][1]+bB1)*xs[s0*132+cB+1];
                        float w10=(acc2[mb2][2*j+1][2]+bB0)*xs[s1*132+cB];
                        float w11=(acc2[mb2][2*j+1][3]+bB1)*xs[s1*132+cB+1];
                        if(k0){ wag[j][0]+=v00; wag[j][1]+=v01; wag[j][2]+=w00; wag[j][3]+=w01; }
                        if(k1){ wag[j][0]+=v10; wag[j][1]+=v11; wag[j][2]+=w10; wag[j][3]+=w11; }
                        u32 h4[4],l4[4];
                        sp2(v00,v01,h4[0],l4[0]); sp2(v10,v11,h4[1],l4[1]);
                        sp2(w00,w01,h4[2],l4[2]); sp2(w10,w11,h4[3],l4[3]);
                        u32* c = base + (hf*4+j)*512 + mb2*128;
                        *(uint4*)(c+lane*4)     = make_uint4(h4[0],h4[1],h4[2],h4[3]);
                        *(uint4*)(c+256+lane*4) = make_uint4(l4[0],l4[1],l4[2],l4[3]);
                    }
                }
                #pragma unroll
                for (int j=0;j<4;++j){
                    #pragma unroll
                    for (int u2=0;u2<4;++u2){
                        float tt=wag[j][u2];
                        tt += __shfl_xor_sync(~0u,tt,4); tt += __shfl_xor_sync(~0u,tt,8); tt += __shfl_xor_sync(~0u,tt,16);
                        wag[j][u2]=tt;
                    }
                    if (lane<4){
                        int cA=hf*64+16*j+2*lane;
                        *(float2*)&sagg[d*132+cA]   = make_float2(wag[j][0],wag[j][1]);
                        *(float2*)&sagg[d*132+cA+8] = make_float2(wag[j][2],wag[j][3]);
                    }
                }
            }
        }
        __syncthreads();
        // ===== node phase =====
        for (int i=tid;i<2048;i+=256){
            int k=i>>4, ch=i&15; u32 dof=k*PIT+ch*16;
            cpa16(sAh+dof, g_Wimg[3][0]+i*16); cpa16(sAl+dof, g_Wimg[3][1]+i*16);
            cpa16(sBh+dof, g_Wimg[4][0]+i*16); cpa16(sBl+dof, g_Wimg[4][1]+i*16);
        }
        CP_COMMIT; CP_WAIT0; __syncthreads();
        {
            float acc[4][4];
            #pragma unroll
            for (int i=0;i<4;++i){acc[i][0]=0;acc[i][1]=0;acc[i][2]=0;acc[i][3]=0;}
            gemm_sm(sagg, sAh, sAl, mb, cg, lane, loff, acc);
            int r0 = mb*16+q, r1 = r0+8;
            #pragma unroll
            for (int jb=0;jb<4;++jb){
                int c = (cg*2+(jb>>1))*16 + (jb&1)*8 + 2*cp;
                float b0v = bb[256+c], b1v = bb[256+c+1];
                *(float2*)&xs[r0*132+c] = make_float2(ssp(acc[jb][0]+b0v), ssp(acc[jb][1]+b1v));
                if (r1 < 24) *(float2*)&xs[r1*132+c] = make_float2(ssp(acc[jb][2]+b0v), ssp(acc[jb][3]+b1v));
            }
        }
        __syncthreads();
        {
            float acc[4][4];
            #pragma unroll
            for (int i=0;i<4;++i){acc[i][0]=0;acc[i][1]=0;acc[i][2]=0;acc[i][3]=0;}
            gemm_sm(xs, sBh, sBl, mb, cg, lane, loff, acc);
            int r0 = mb*16+q, r1 = r0+8;
            #pragma unroll
            for (int jb=0;jb<4;++jb){
                int c = (cg*2+(jb>>1))*16 + (jb&1)*8 + 2*cp;
                float b0v = bb[384+c], b1v = bb[384+c+1];
                float2 h0 = *(float2*)&hs[r0*132+c];
                h0.x += acc[jb][0]+b0v; h0.y += acc[jb][1]+b1v;
                *(float2*)&hs[r0*132+c] = h0;
                if (r1 < 24){
                    float2 h1 = *(float2*)&hs[r1*132+c];
                    h1.x += acc[jb][2]+b0v; h1.y += acc[jb][3]+b1v;
                    *(float2*)&hs[r1*132+c] = h1;
                }
            }
        }
        __syncthreads();
    }

    // ===== graph readout =====
    float* w1s = (float*)WAh;
    for (int i=tid;i<2048;i+=256) ((float4*)w1s)[i] = ((const float4*)gw1)[i];
    __syncthreads();
    float local = 0.f;
    for (int pos = tid; pos < Aat*64; pos += 256){
        int s = pos >> 6, c = pos & 63;
        float acc = gb1[c];
        #pragma unroll 16
        for (int k = 0; k < 128; ++k) acc += hs[s*132+k] * w1s[k*64+c];
        local += ssp(acc) * gw2[c];
    }
    float* red = sagg;
    red[tid] = local;
    __syncthreads();
    #pragma unroll
    for (int off = 128; off > 0; off >>= 1){
        if (tid < off) red[tid] += red[tid+off];
        __syncthreads();
    }
    if (tid == 0) out[m] = red[0] + (float)Aat * gb2[0];
}

extern "C" void kernel_launch(void* const* d_in, const int* in_sizes, int n_in,
                              void* d_out, int out_size)
{
    const int*   charges = (const int*)  d_in[0];
    const float* coords  = (const float*)d_in[1];
    const float* emb = (const float*)d_in[4];
    const float* nlw = (const float*)d_in[5];
    const float* ew1 = (const float*)d_in[6];
    const float* eb1 = (const float*)d_in[7];
    const float* ew2 = (const float*)d_in[8];
    const float* eb2 = (const float*)d_in[9];
    const float* nw1 = (const float*)d_in[10];
    const float* nb1 = (const float*)d_in[11];
    const float* nw2 = (const float*)d_in[12];
    const float* nb2 = (const float*)d_in[13];
    const float* gw1 = (const float*)d_in[14];
    const float* gb1 = (const float*)d_in[15];
    const float* gw2 = (const float*)d_in[16];
    const float* gb2 = (const float*)d_in[17];
    float* out = (float*)d_out;

    const int SMF = 4*IMG + (24*132 + 32*132 + 24*132 + 512)*4;  // 183552
    cudaFuncSetAttribute(k_fused, cudaFuncAttributeMaxDynamicSharedMemorySize, SMF);

    k_init <<<5, 128>>>(nlw, ew1, ew2, nw1, nw2);
    k_fused<<<Mmol, 256, SMF>>>(charges, coords, emb, eb1, eb2, nb1, nb2,
                                gw1, gb1, gw2, gb2, out);
}

// round 11
// speedup vs baseline: 1.1489x; 1.1489x over previous
#include <cuda_runtime.h>
#include <cuda_bf16.h>

typedef unsigned int u32; typedef unsigned long long u64;
#define Mmol 2048
#define Aat 24
#define PIT 272
#define IMG 34816
#define NT 384

__device__ u32 g_EAf[(size_t)Mmol*24*4096];
__device__ __align__(16) unsigned char g_Wimg[5][2][32768];

__device__ __forceinline__ u32 smaddr(const void* p){
    u32 a; asm("{ .reg .u64 t; cvta.to.shared.u64 t, %1; cvt.u32.u64 %0, t; }" : "=r"(a) : "l"(p)); return a;
}
__device__ __forceinline__ float ssp(float x){
    return fmaxf(x, 0.f) + __logf(1.f + __expf(-fabsf(x))) - 0.6931471805599453f;
}
__device__ __forceinline__ void cpa16(u32 dst, const void* src){
    asm volatile("cp.async.cg.shared.global [%0], [%1], 16;" :: "r"(dst), "l"(src) : "memory");
}
#define CP_COMMIT asm volatile("cp.async.commit_group;" ::: "memory")
#define CP_WAIT0  asm volatile("cp.async.wait_group 0;"  ::: "memory")
__device__ __forceinline__ void ldsm4t(u32* r, u32 a){
    asm volatile("ldmatrix.sync.aligned.m8n8.x4.trans.shared.b16 {%0,%1,%2,%3}, [%4];"
        : "=r"(r[0]),"=r"(r[1]),"=r"(r[2]),"=r"(r[3]) : "r"(a));
}
__device__ __forceinline__ void mma_bf(float* d, const u32* a, u32 b0, u32 b1){
    asm volatile("mma.sync.aligned.m16n8k16.row.col.f32.bf16.bf16.f32 "
        "{%0,%1,%2,%3}, {%4,%5,%6,%7}, {%8,%9}, {%0,%1,%2,%3};"
        : "+f"(d[0]),"+f"(d[1]),"+f"(d[2]),"+f"(d[3])
        : "r"(a[0]),"r"(a[1]),"r"(a[2]),"r"(a[3]),"r"(b0),"r"(b1));
}
__device__ __forceinline__ void sp2(float x, float y, u32& h, u32& l){
    __nv_bfloat162 hb = __floats2bfloat162_rn(x, y);
    __nv_bfloat162 lb = __floats2bfloat162_rn(x - __bfloat162float(hb.x), y - __bfloat162float(hb.y));
    h = *(u32*)&hb; l = *(u32*)&lb;
}

__global__ void k_init(const float* nlw, const float* ew1, const float* ew2,
                       const float* nw1, const float* nw2){
    const float* srcs[5] = {nlw, ew1, ew2, nw1, nw2};
    const float* src = srcs[blockIdx.x];
    int n = threadIdx.x;
    for (int k = 0; k < 128; ++k){
        float v = src[k*128 + n];
        __nv_bfloat16 h = __float2bfloat16_rn(v);
        __nv_bfloat16 l = __float2bfloat16_rn(v - __bfloat162float(h));
        *(__nv_bfloat16*)(g_Wimg[blockIdx.x][0] + k*256 + n*2) = h;
        *(__nv_bfloat16*)(g_Wimg[blockIdx.x][1] + k*256 + n*2) = l;
    }
}

// small M=32 x N=128 GEMM from fp32 smem rows (warps 0-7 only)
__device__ __forceinline__ void gemm_sm(const float* abuf, u32 bhi, u32 bli,
                                        int mb, int cg, int lane, u32 loff, float acc[4][4]){
    const int q = lane>>2, cp = lane&3;
    const int r0 = mb*16 + q, r1 = r0 + 8;
    const bool ok1 = (r1 < 24);
    #pragma unroll
    for (int ks=0; ks<8; ++ks){
        int kc = 16*ks + 2*cp;
        float2 v0 = *(const float2*)&abuf[r0*132+kc];
        float2 v1 = ok1 ? *(const float2*)&abuf[r1*132+kc] : make_float2(0.f,0.f);
        float2 v2 = *(const float2*)&abuf[r0*132+kc+8];
        float2 v3 = ok1 ? *(const float2*)&abuf[r1*132+kc+8] : make_float2(0.f,0.f);
        u32 ah[4], al[4];
        sp2(v0.x,v0.y,ah[0],al[0]); sp2(v1.x,v1.y,ah[1],al[1]);
        sp2(v2.x,v2.y,ah[2],al[2]); sp2(v3.x,v3.y,ah[3],al[3]);
        #pragma unroll
        for (int j=0;j<2;++j){
            u32 bh[4],bl[4]; u32 ba = loff + ks*(16*PIT) + (cg*2+j)*32;
            ldsm4t(bh, bhi+ba); ldsm4t(bl, bli+ba);
            mma_bf(acc[2*j],   ah, bh[0], bh[1]);
            mma_bf(acc[2*j],   ah, bl[0], bl[1]);
            mma_bf(acc[2*j],   al, bh[0], bh[1]);
            mma_bf(acc[2*j+1], ah, bh[2], bh[3]);
            mma_bf(acc[2*j+1], ah, bl[2], bl[3]);
            mma_bf(acc[2*j+1], al, bh[2], bh[3]);
        }
    }
}

__global__ void __launch_bounds__(NT,1) k_fused(
    const int* __restrict__ charges, const float* __restrict__ coords,
    const float* __restrict__ emb,
    const float* __restrict__ eb1, const float* __restrict__ eb2,
    const float* __restrict__ nb1, const float* __restrict__ nb2,
    const float* __restrict__ gw1, const float* __restrict__ gb1,
    const float* __restrict__ gw2, const float* __restrict__ gb2,
    float* __restrict__ out)
{
    extern __shared__ __align__(16) char sm[];
    char *WAh = sm, *WAl = sm+IMG, *WBh = sm+2*IMG, *WBl = sm+3*IMG;
    float* hs    = (float*)(sm + 4*IMG);   // 24x132
    float* xs    = hs + 24*132;            // 32x132 (rows 24-31 zero)
    float* sagg  = xs + 32*132;            // 24x132
    float* sagg2 = sagg + 24*132;          // 2 x 24x132
    float* bb    = sagg2 + 2*24*132;       // 512
    const int tid = threadIdx.x, m = blockIdx.x;
    const int wid = tid>>5, lane = tid&31, q = lane>>2, cp = lane&3;
    const u32 loff = (lane&15)*PIT + (lane>>4)*16;
    const u32 sAh = smaddr(WAh), sAl = smaddr(WAl), sBh = smaddr(WBh), sBl = smaddr(WBl);

    for (int i = tid; i < Aat*128; i += NT)
        hs[(i>>7)*132 + (i&127)] = emb[charges[m*Aat + (i>>7)]*128 + (i&127)];
    for (int i = tid; i < 8*132; i += NT) xs[24*132 + i] = 0.f;
    if (tid < 128){ bb[tid]=eb1[tid]; bb[128+tid]=eb2[tid]; bb[256+tid]=nb1[tid]; bb[384+tid]=nb2[tid]; }

    // RBF -> EA fragments (2 d's per warp)
    {
        const float* cm = coords + (size_t)m*72;
        for (int i2 = 0; i2 < 2; ++i2){
            int d = wid + 12*i2;
            float ddx=cm[d*3], ddy=cm[d*3+1], ddz=cm[d*3+2];
            float dv[3];
            #pragma unroll
            for (int i=0;i<3;++i){
                int s = q + i*8;
                float ax=cm[s*3]-ddx, ay=cm[s*3+1]-ddy, az=cm[s*3+2]-ddz;
                dv[i] = sqrtf(ax*ax+ay*ay+az*az);
            }
            const float delta = 10.f/127.f, coeff = -0.5f/(delta*delta);
            u32* base = g_EAf + ((size_t)(m*24+d))*4096;
            #pragma unroll
            for (int ks=0; ks<8; ++ks){
                float c0 = (float)(16*ks + 2*cp);
                float v[3][4];
                #pragma unroll
                for (int i=0;i<3;++i)
                    #pragma unroll
                    for (int j=0;j<4;++j){
                        float od = dv[i] - delta*(c0 + (float)((j>>1)*8 + (j&1)));
                        v[i][j] = (fabsf(od) < 1.2f) ? __expf(coeff*od*od) : 0.f;
                    }
                u32 h[4],l[4],h2[4],l2[4];
                sp2(v[0][0],v[0][1],h[0],l[0]);  sp2(v[1][0],v[1][1],h[1],l[1]);
                sp2(v[0][2],v[0][3],h[2],l[2]);  sp2(v[1][2],v[1][3],h[3],l[3]);
                sp2(v[2][0],v[2][1],h2[0],l2[0]); h2[1]=0; l2[1]=0;
                sp2(v[2][2],v[2][3],h2[2],l2[2]); h2[3]=0; l2[3]=0;
                u32* c = base + ks*512;
                *(uint4*)(c + lane*4)       = make_uint4(h[0],h[1],h[2],h[3]);
                *(uint4*)(c + 128 + lane*4) = make_uint4(h2[0],h2[1],h2[2],h2[3]);
                *(uint4*)(c + 256 + lane*4) = make_uint4(l[0],l[1],l[2],l[3]);
                *(uint4*)(c + 384 + lane*4) = make_uint4(l2[0],l2[1],l2[2],l2[3]);
            }
        }
    }

    const float* b1s = bb;
    const float* b2s = bb + 128;

    for (int layer = 0; layer < 4; ++layer){
        // ===== x = h @ nlw =====
        for (int i=tid;i<2048;i+=NT){
            int k=i>>4, ch=i&15; u32 dof=k*PIT+ch*16;
            cpa16(sAh+dof, g_Wimg[0][0]+i*16); cpa16(sAl+dof, g_Wimg[0][1]+i*16);
        }
        CP_COMMIT; CP_WAIT0; __syncthreads();
        if (wid < 8){
            const int mb = wid & 1, cg = wid >> 1;
            float acc[4][4];
            #pragma unroll
            for (int i=0;i<4;++i){acc[i][0]=0;acc[i][1]=0;acc[i][2]=0;acc[i][3]=0;}
            gemm_sm(hs, sAh, sAl, mb, cg, lane, loff, acc);
            int r0 = mb*16+q, r1 = r0+8;
            #pragma unroll
            for (int jb=0;jb<4;++jb){
                int c = (cg*2+(jb>>1))*16 + (jb&1)*8 + 2*cp;
                *(float2*)&xs[r0*132+c] = make_float2(acc[jb][0], acc[jb][1]);
                if (r1 < 24) *(float2*)&xs[r1*132+c] = make_float2(acc[jb][2], acc[jb][3]);
            }
        }
        __syncthreads();
        // ===== edge phase: 48 tasks (d, half-16), 12 warps x 4 passes =====
        for (int i=tid;i<2048;i+=NT){
            int k=i>>4, ch=i&15; u32 dof=k*PIT+ch*16;
            cpa16(sAh+dof, g_Wimg[1][0]+i*16); cpa16(sAl+dof, g_Wimg[1][1]+i*16);
            cpa16(sBh+dof, g_Wimg[2][0]+i*16); cpa16(sBl+dof, g_Wimg[2][1]+i*16);
        }
        CP_COMMIT; CP_WAIT0; __syncthreads();
        for (int pass=0; pass<4; ++pass){
            const int task = pass*12 + wid;
            const int d = task >> 1, half = task & 1;
            u32* base = g_EAf + ((size_t)(m*24+d))*4096 + half*128;
            const int s0 = half*16 + q, s1 = s0 + 8;

            // GEMM1: A = EA fragments (global, L2-hot)
            float acc1[16][4];
            #pragma unroll
            for (int i=0;i<16;++i){acc1[i][0]=0;acc1[i][1]=0;acc1[i][2]=0;acc1[i][3]=0;}
            uint4 H = *(const uint4*)(base + lane*4);
            uint4 L = *(const uint4*)(base + 256 + lane*4);
            #pragma unroll
            for (int ks=0;ks<8;++ks){
                uint4 nH, nL;
                if (ks<7){
                    nH = *(const uint4*)(base + (ks+1)*512 + lane*4);
                    nL = *(const uint4*)(base + (ks+1)*512 + 256 + lane*4);
                }
                u32 ah[4]={H.x,H.y,H.z,H.w}, al[4]={L.x,L.y,L.z,L.w};
                #pragma unroll
                for (int j=0;j<8;++j){
                    u32 bh[4],bl[4]; u32 ba=loff+ks*(16*PIT)+j*32;
                    ldsm4t(bh,sAh+ba); ldsm4t(bl,sAl+ba);
                    mma_bf(acc1[2*j],   ah,bh[0],bh[1]); mma_bf(acc1[2*j],   ah,bl[0],bl[1]); mma_bf(acc1[2*j],   al,bh[0],bh[1]);
                    mma_bf(acc1[2*j+1], ah,bh[2],bh[3]); mma_bf(acc1[2*j+1], ah,bl[2],bl[3]); mma_bf(acc1[2*j+1], al,bh[2],bh[3]);
                }
                if (ks<7){ H=nH; L=nL; }
            }
            // mid = ssp(acc1+b1) -> A2 fragments (C-layout == A-layout)
            u32 a2h[8][4], a2l[8][4];
            #pragma unroll
            for (int j=0;j<8;++j){
                int c0=16*j+2*cp;
                float bA0=b1s[c0], bA1=b1s[c0+1], bB0=b1s[c0+8], bB1=b1s[c0+9];
                sp2(ssp(acc1[2*j][0]+bA0),   ssp(acc1[2*j][1]+bA1),   a2h[j][0], a2l[j][0]);
                sp2(ssp(acc1[2*j][2]+bA0),   ssp(acc1[2*j][3]+bA1),   a2h[j][1], a2l[j][1]);
                sp2(ssp(acc1[2*j+1][0]+bB0), ssp(acc1[2*j+1][1]+bB1), a2h[j][2], a2l[j][2]);
                sp2(ssp(acc1[2*j+1][2]+bB0), ssp(acc1[2*j+1][3]+bB1), a2h[j][3], a2l[j][3]);
            }
            // GEMM2 (reuse acc1 as acc2)
            #pragma unroll
            for (int i=0;i<16;++i){acc1[i][0]=0;acc1[i][1]=0;acc1[i][2]=0;acc1[i][3]=0;}
            #pragma unroll
            for (int ks=0;ks<8;++ks)
                #pragma unroll
                for (int j=0;j<8;++j){
                    u32 bh[4],bl[4]; u32 ba=loff+ks*(16*PIT)+j*32;
                    ldsm4t(bh,sBh+ba); ldsm4t(bl,sBl+ba);
                    mma_bf(acc1[2*j],   a2h[ks],bh[0],bh[1]); mma_bf(acc1[2*j],   a2h[ks],bl[0],bl[1]); mma_bf(acc1[2*j],   a2l[ks],bh[0],bh[1]);
                    mma_bf(acc1[2*j+1], a2h[ks],bh[2],bh[3]); mma_bf(acc1[2*j+1], a2h[ks],bl[2],bl[3]); mma_bf(acc1[2*j+1], a2l[ks],bh[2],bh[3]);
                }
            // epilogue: *x[s], store EA fragments, shuffle-agg into sagg2[half]
            const bool k0 = (s0 < 24) && (s0 != d);
            const bool k1 = (s1 < 24) && (s1 != d);
            float* agp = sagg2 + half*24*132 + d*132;
            #pragma unroll
            for (int j=0;j<8;++j){
                int cA=16*j+2*cp, cB=cA+8;
                float bA0=b2s[cA],bA1=b2s[cA+1],bB0=b2s[cB],bB1=b2s[cB+1];
                float v00=(acc1[2*j][0]+bA0)*xs[s0*132+cA];
                float v01=(acc1[2*j][1]+bA1)*xs[s0*132+cA+1];
                float v10=(acc1[2*j][2]+bA0)*xs[s1*132+cA];
                float v11=(acc1[2*j][3]+bA1)*xs[s1*132+cA+1];
                float w00=(acc1[2*j+1][0]+bB0)*xs[s0*132+cB];
                float w01=(acc1[2*j+1][1]+bB1)*xs[s0*132+cB+1];
                float w10=(acc1[2*j+1][2]+bB0)*xs[s1*132+cB];
                float w11=(acc1[2*j+1][3]+bB1)*xs[s1*132+cB+1];
                u32 h4[4],l4[4];
                sp2(v00,v01,h4[0],l4[0]); sp2(v10,v11,h4[1],l4[1]);
                sp2(w00,w01,h4[2],l4[2]); sp2(w10,w11,h4[3],l4[3]);
                u32* c = base + j*512;
                *(uint4*)(c+lane*4)     = make_uint4(h4[0],h4[1],h4[2],h4[3]);
                *(uint4*)(c+256+lane*4) = make_uint4(l4[0],l4[1],l4[2],l4[3]);
                float g0 = (k0?v00:0.f) + (k1?v10:0.f);
                float g1 = (k0?v01:0.f) + (k1?v11:0.f);
                float g2 = (k0?w00:0.f) + (k1?w10:0.f);
                float g3 = (k0?w01:0.f) + (k1?w11:0.f);
                g0 += __shfl_xor_sync(~0u,g0,4); g0 += __shfl_xor_sync(~0u,g0,8); g0 += __shfl_xor_sync(~0u,g0,16);
                g1 += __shfl_xor_sync(~0u,g1,4); g1 += __shfl_xor_sync(~0u,g1,8); g1 += __shfl_xor_sync(~0u,g1,16);
                g2 += __shfl_xor_sync(~0u,g2,4); g2 += __shfl_xor_sync(~0u,g2,8); g2 += __shfl_xor_sync(~0u,g2,16);
                g3 += __shfl_xor_sync(~0u,g3,4); g3 += __shfl_xor_sync(~0u,g3,8); g3 += __shfl_xor_sync(~0u,g3,16);
                if (lane < 4){
                    *(float2*)&agp[16*j + 2*lane]     = make_float2(g0, g1);
                    *(float2*)&agp[16*j + 8 + 2*lane] = make_float2(g2, g3);
                }
            }
        }
        __syncthreads();
        // combine halves
        for (int i=tid;i<Aat*128;i+=NT){
            int dd=i>>7, c=i&127;
            sagg[dd*132+c] = sagg2[dd*132+c] + sagg2[24*132 + dd*132+c];
        }
        // ===== node phase =====
        for (int i=tid;i<2048;i+=NT){
            int k=i>>4, ch=i&15; u32 dof=k*PIT+ch*16;
            cpa16(sAh+dof, g_Wimg[3][0]+i*16); cpa16(sAl+dof, g_Wimg[3][1]+i*16);
            cpa16(sBh+dof, g_Wimg[4][0]+i*16); cpa16(sBl+dof, g_Wimg[4][1]+i*16);
        }
        CP_COMMIT; CP_WAIT0; __syncthreads();
        if (wid < 8){
            const int mb = wid & 1, cg = wid >> 1;
            float acc[4][4];
            #pragma unroll
            for (int i=0;i<4;++i){acc[i][0]=0;acc[i][1]=0;acc[i][2]=0;acc[i][3]=0;}
            gemm_sm(sagg, sAh, sAl, mb, cg, lane, loff, acc);
            int r0 = mb*16+q, r1 = r0+8;
            #pragma unroll
            for (int jb=0;jb<4;++jb){
                int c = (cg*2+(jb>>1))*16 + (jb&1)*8 + 2*cp;
                float b0v = bb[256+c], b1v = bb[256+c+1];
                *(float2*)&xs[r0*132+c] = make_float2(ssp(acc[jb][0]+b0v), ssp(acc[jb][1]+b1v));
                if (r1 < 24) *(float2*)&xs[r1*132+c] = make_float2(ssp(acc[jb][2]+b0v), ssp(acc[jb][3]+b1v));
            }
        }
        __syncthreads();
        if (wid < 8){
            const int mb = wid & 1, cg = wid >> 1;
            float acc[4][4];
            #pragma unroll
            for (int i=0;i<4;++i){acc[i][0]=0;acc[i][1]=0;acc[i][2]=0;acc[i][3]=0;}
            gemm_sm(xs, sBh, sBl, mb, cg, lane, loff, acc);
            int r0 = mb*16+q, r1 = r0+8;
            #pragma unroll
            for (int jb=0;jb<4;++jb){
                int c = (cg*2+(jb>>1))*16 + (jb&1)*8 + 2*cp;
                float b0v = bb[384+c], b1v = bb[384+c+1];
                float2 h0 = *(float2*)&hs[r0*132+c];
                h0.x += acc[jb][0]+b0v; h0.y += acc[jb][1]+b1v;
                *(float2*)&hs[r0*132+c] = h0;
                if (r1 < 24){
                    float2 h1 = *(float2*)&hs[r1*132+c];
                    h1.x += acc[jb][2]+b0v; h1.y += acc[jb][3]+b1v;
                    *(float2*)&hs[r1*132+c] = h1;
                }
            }
        }
        __syncthreads();
    }

    // ===== graph readout =====
    float* w1s = (float*)WAh;
    for (int i=tid;i<2048;i+=NT) ((float4*)w1s)[i] = ((const float4*)gw1)[i];
    __syncthreads();
    float local = 0.f;
    for (int pos = tid; pos < Aat*64; pos += NT){
        int s = pos >> 6, c = pos & 63;
        float acc = gb1[c];
        #pragma unroll 16
        for (int k = 0; k < 128; ++k) acc += hs[s*132+k] * w1s[k*64+c];
        local += ssp(acc) * gw2[c];
    }
    float* red = sagg;
    red[tid] = local;
    if (tid < 128) red[NT + tid] = 0.f;
    __syncthreads();
    #pragma unroll
    for (int off = 256; off > 0; off >>= 1){
        if (tid < off) red[tid] += red[tid+off];
        __syncthreads();
    }
    if (tid == 0) out[m] = red[0] + (float)Aat * gb2[0];
}

extern "C" void kernel_launch(void* const* d_in, const int* in_sizes, int n_in,
                              void* d_out, int out_size)
{
    const int*   charges = (const int*)  d_in[0];
    const float* coords  = (const float*)d_in[1];
    const float* emb = (const float*)d_in[4];
    const float* nlw = (const float*)d_in[5];
    const float* ew1 = (const float*)d_in[6];
    const float* eb1 = (const float*)d_in[7];
    const float* ew2 = (const float*)d_in[8];
    const float* eb2 = (const float*)d_in[9];
    const float* nw1 = (const float*)d_in[10];
    const float* nb1 = (const float*)d_in[11];
    const float* nw2 = (const float*)d_in[12];
    const float* nb2 = (const float*)d_in[13];
    const float* gw1 = (const float*)d_in[14];
    const float* gb1 = (const float*)d_in[15];
    const float* gw2 = (const float*)d_in[16];
    const float* gb2 = (const float*)d_in[17];
    float* out = (float*)d_out;

    const int SMF = 4*IMG + (24*132 + 32*132 + 24*132 + 2*24*132 + 512)*4;  // 196224
    cudaFuncSetAttribute(k_fused, cudaFuncAttributeMaxDynamicSharedMemorySize, SMF);

    k_init <<<5, 128>>>(nlw, ew1, ew2, nw1, nw2);
    k_fused<<<Mmol, NT, SMF>>>(charges, coords, emb, eb1, eb2, nb1, nb2,
                               gw1, gb1, gw2, gb2, out);
}

// round 12
// speedup vs baseline: 1.5238x; 1.3262x over previous
#include <cuda_runtime.h>
#include <cuda_fp16.h>

typedef unsigned int u32; typedef unsigned long long u64;
#define Mmol 2048
#define Aat 24
#define PIT 272
#define IMG 34816
#define NT 384

// EA fragments per (m,d): 8 ks-chunks of 512 u32 [hi mb0|hi mb1|lo mb0|lo mb1], fp16 pairs
__device__ u32 g_EAf[(size_t)Mmol*24*4096];
__device__ __align__(16) unsigned char g_Wimg[5][32768];   // single fp16 images

__device__ __forceinline__ u32 smaddr(const void* p){
    u32 a; asm("{ .reg .u64 t; cvta.to.shared.u64 t, %1; cvt.u32.u64 %0, t; }" : "=r"(a) : "l"(p)); return a;
}
__device__ __forceinline__ float ssp(float x){
    return fmaxf(x, 0.f) + __logf(1.f + __expf(-fabsf(x))) - 0.6931471805599453f;
}
__device__ __forceinline__ void cpa16(u32 dst, const void* src){
    asm volatile("cp.async.cg.shared.global [%0], [%1], 16;" :: "r"(dst), "l"(src) : "memory");
}
#define CP_COMMIT asm volatile("cp.async.commit_group;" ::: "memory")
#define CP_WAIT0  asm volatile("cp.async.wait_group 0;"  ::: "memory")
__device__ __forceinline__ void ldsm4t(u32* r, u32 a){
    asm volatile("ldmatrix.sync.aligned.m8n8.x4.trans.shared.b16 {%0,%1,%2,%3}, [%4];"
        : "=r"(r[0]),"=r"(r[1]),"=r"(r[2]),"=r"(r[3]) : "r"(a));
}
__device__ __forceinline__ void mma_hf(float* d, const u32* a, u32 b0, u32 b1){
    asm volatile("mma.sync.aligned.m16n8k16.row.col.f32.f16.f16.f32 "
        "{%0,%1,%2,%3}, {%4,%5,%6,%7}, {%8,%9}, {%0,%1,%2,%3};"
        : "+f"(d[0]),"+f"(d[1]),"+f"(d[2]),"+f"(d[3])
        : "r"(a[0]),"r"(a[1]),"r"(a[2]),"r"(a[3]),"r"(b0),"r"(b1));
}
// fp16 hi/lo split of a float pair
__device__ __forceinline__ void sp2h(float x, float y, u32& h, u32& l){
    __half2 hb = __floats2half2_rn(x, y);
    float2 hf = __half22float2(hb);
    __half2 lb = __floats2half2_rn(x - hf.x, y - hf.y);
    h = *(u32*)&hb; l = *(u32*)&lb;
}

__global__ void k_init(const float* nlw, const float* ew1, const float* ew2,
                       const float* nw1, const float* nw2){
    const float* srcs[5] = {nlw, ew1, ew2, nw1, nw2};
    const float* src = srcs[blockIdx.x];
    int n = threadIdx.x;
    for (int k = 0; k < 128; ++k)
        *(__half*)(g_Wimg[blockIdx.x] + k*256 + n*2) = __float2half_rn(src[k*128 + n]);
}

// M=32 x N=128 GEMM from fp32 smem rows, 2-term fp16 (warps 0-7)
__device__ __forceinline__ void gemm_sm(const float* abuf, u32 bimg,
                                        int mb, int cg, int lane, u32 loff, float acc[4][4]){
    const int q = lane>>2, cp = lane&3;
    const int r0 = mb*16 + q, r1 = r0 + 8;
    const bool ok1 = (r1 < 24);
    #pragma unroll
    for (int ks=0; ks<8; ++ks){
        int kc = 16*ks + 2*cp;
        float2 v0 = *(const float2*)&abuf[r0*132+kc];
        float2 v1 = ok1 ? *(const float2*)&abuf[r1*132+kc] : make_float2(0.f,0.f);
        float2 v2 = *(const float2*)&abuf[r0*132+kc+8];
        float2 v3 = ok1 ? *(const float2*)&abuf[r1*132+kc+8] : make_float2(0.f,0.f);
        u32 ah[4], al[4];
        sp2h(v0.x,v0.y,ah[0],al[0]); sp2h(v1.x,v1.y,ah[1],al[1]);
        sp2h(v2.x,v2.y,ah[2],al[2]); sp2h(v3.x,v3.y,ah[3],al[3]);
        #pragma unroll
        for (int j=0;j<2;++j){
            u32 bh[4]; u32 ba = loff + ks*(16*PIT) + (cg*2+j)*32;
            ldsm4t(bh, bimg+ba);
            mma_hf(acc[2*j],   ah, bh[0], bh[1]);
            mma_hf(acc[2*j],   al, bh[0], bh[1]);
            mma_hf(acc[2*j+1], ah, bh[2], bh[3]);
            mma_hf(acc[2*j+1], al, bh[2], bh[3]);
        }
    }
}

__global__ void __launch_bounds__(NT,1) k_fused(
    const int* __restrict__ charges, const float* __restrict__ coords,
    const float* __restrict__ emb,
    const float* __restrict__ eb1, const float* __restrict__ eb2,
    const float* __restrict__ nb1, const float* __restrict__ nb2,
    const float* __restrict__ gw1, const float* __restrict__ gb1,
    const float* __restrict__ gw2, const float* __restrict__ gb2,
    float* __restrict__ out)
{
    extern __shared__ __align__(16) char sm[];
    char *WA = sm, *WB = sm+IMG;
    float* hs    = (float*)(sm + 2*IMG);   // 24x132
    float* xs    = hs + 24*132;            // 32x132 (rows 24-31 zero)
    float* sagg  = xs + 32*132;            // 24x132
    float* sagg2 = sagg + 24*132;          // 2 x 24x132
    float* bb    = sagg2 + 2*24*132;       // 512
    const int tid = threadIdx.x, m = blockIdx.x;
    const int wid = tid>>5, lane = tid&31, q = lane>>2, cp = lane&3;
    const u32 loff = (lane&15)*PIT + (lane>>4)*16;
    const u32 sWA = smaddr(WA), sWB = smaddr(WB);

    for (int i = tid; i < Aat*128; i += NT)
        hs[(i>>7)*132 + (i&127)] = emb[charges[m*Aat + (i>>7)]*128 + (i&127)];
    for (int i = tid; i < 8*132; i += NT) xs[24*132 + i] = 0.f;
    if (tid < 128){ bb[tid]=eb1[tid]; bb[128+tid]=eb2[tid]; bb[256+tid]=nb1[tid]; bb[384+tid]=nb2[tid]; }

    // RBF -> EA fragments (2 d's per warp), fp16 hi/lo
    {
        const float* cm = coords + (size_t)m*72;
        for (int i2 = 0; i2 < 2; ++i2){
            int d = wid + 12*i2;
            float ddx=cm[d*3], ddy=cm[d*3+1], ddz=cm[d*3+2];
            float dv[3];
            #pragma unroll
            for (int i=0;i<3;++i){
                int s = q + i*8;
                float ax=cm[s*3]-ddx, ay=cm[s*3+1]-ddy, az=cm[s*3+2]-ddz;
                dv[i] = sqrtf(ax*ax+ay*ay+az*az);
            }
            const float delta = 10.f/127.f, coeff = -0.5f/(delta*delta);
            u32* base = g_EAf + ((size_t)(m*24+d))*4096;
            #pragma unroll
            for (int ks=0; ks<8; ++ks){
                float c0 = (float)(16*ks + 2*cp);
                float v[3][4];
                #pragma unroll
                for (int i=0;i<3;++i)
                    #pragma unroll
                    for (int j=0;j<4;++j){
                        float od = dv[i] - delta*(c0 + (float)((j>>1)*8 + (j&1)));
                        v[i][j] = (fabsf(od) < 1.2f) ? __expf(coeff*od*od) : 0.f;
                    }
                u32 h[4],l[4],h2[4],l2[4];
                sp2h(v[0][0],v[0][1],h[0],l[0]);  sp2h(v[1][0],v[1][1],h[1],l[1]);
                sp2h(v[0][2],v[0][3],h[2],l[2]);  sp2h(v[1][2],v[1][3],h[3],l[3]);
                sp2h(v[2][0],v[2][1],h2[0],l2[0]); h2[1]=0; l2[1]=0;
                sp2h(v[2][2],v[2][3],h2[2],l2[2]); h2[3]=0; l2[3]=0;
                u32* c = base + ks*512;
                *(uint4*)(c + lane*4)       = make_uint4(h[0],h[1],h[2],h[3]);
                *(uint4*)(c + 128 + lane*4) = make_uint4(h2[0],h2[1],h2[2],h2[3]);
                *(uint4*)(c + 256 + lane*4) = make_uint4(l[0],l[1],l[2],l[3]);
                *(uint4*)(c + 384 + lane*4) = make_uint4(l2[0],l2[1],l2[2],l2[3]);
            }
        }
    }

    const float* b1s = bb;
    const float* b2s = bb + 128;

    for (int layer = 0; layer < 4; ++layer){
        // ===== x = h @ nlw =====
        for (int i=tid;i<2048;i+=NT){
            int k=i>>4, ch=i&15;
            cpa16(sWA + k*PIT+ch*16, g_Wimg[0]+i*16);
        }
        CP_COMMIT; CP_WAIT0; __syncthreads();
        if (wid < 8){
            const int mb = wid & 1, cg = wid >> 1;
            float acc[4][4];
            #pragma unroll
            for (int i=0;i<4;++i){acc[i][0]=0;acc[i][1]=0;acc[i][2]=0;acc[i][3]=0;}
            gemm_sm(hs, sWA, mb, cg, lane, loff, acc);
            int r0 = mb*16+q, r1 = r0+8;
            #pragma unroll
            for (int jb=0;jb<4;++jb){
                int c = (cg*2+(jb>>1))*16 + (jb&1)*8 + 2*cp;
                *(float2*)&xs[r0*132+c] = make_float2(acc[jb][0], acc[jb][1]);
                if (r1 < 24) *(float2*)&xs[r1*132+c] = make_float2(acc[jb][2], acc[jb][3]);
            }
        }
        __syncthreads();
        // ===== edge phase: 48 half-tasks, 12 warps x 4 passes =====
        for (int i=tid;i<2048;i+=NT){
            int k=i>>4, ch=i&15; u32 dof=k*PIT+ch*16;
            cpa16(sWA+dof, g_Wimg[1]+i*16);
            cpa16(sWB+dof, g_Wimg[2]+i*16);
        }
        CP_COMMIT; CP_WAIT0; __syncthreads();
        for (int pass=0; pass<4; ++pass){
            const int task = pass*12 + wid;
            const int d = task >> 1, half = task & 1;
            u32* base = g_EAf + ((size_t)(m*24+d))*4096 + half*128;
            const int s0 = half*16 + q, s1 = s0 + 8;

            // GEMM1: A = EA fragments (L2-hot), 2-term fp16
            float acc1[16][4];
            #pragma unroll
            for (int i=0;i<16;++i){acc1[i][0]=0;acc1[i][1]=0;acc1[i][2]=0;acc1[i][3]=0;}
            uint4 H = *(const uint4*)(base + lane*4);
            uint4 L = *(const uint4*)(base + 256 + lane*4);
            #pragma unroll
            for (int ks=0;ks<8;++ks){
                uint4 nH, nL;
                if (ks<7){
                    nH = *(const uint4*)(base + (ks+1)*512 + lane*4);
                    nL = *(const uint4*)(base + (ks+1)*512 + 256 + lane*4);
                }
                u32 ah[4]={H.x,H.y,H.z,H.w}, al[4]={L.x,L.y,L.z,L.w};
                #pragma unroll
                for (int j=0;j<8;++j){
                    u32 bh[4]; u32 ba=loff+ks*(16*PIT)+j*32;
                    ldsm4t(bh,sWA+ba);
                    mma_hf(acc1[2*j],   ah,bh[0],bh[1]); mma_hf(acc1[2*j],   al,bh[0],bh[1]);
                    mma_hf(acc1[2*j+1], ah,bh[2],bh[3]); mma_hf(acc1[2*j+1], al,bh[2],bh[3]);
                }
                if (ks<7){ H=nH; L=nL; }
            }
            // mid = ssp(acc1+b1) -> A2 fragments (fp16 hi/lo)
            u32 a2h[8][4], a2l[8][4];
            #pragma unroll
            for (int j=0;j<8;++j){
                int c0=16*j+2*cp;
                float bA0=b1s[c0], bA1=b1s[c0+1], bB0=b1s[c0+8], bB1=b1s[c0+9];
                sp2h(ssp(acc1[2*j][0]+bA0),   ssp(acc1[2*j][1]+bA1),   a2h[j][0], a2l[j][0]);
                sp2h(ssp(acc1[2*j][2]+bA0),   ssp(acc1[2*j][3]+bA1),   a2h[j][1], a2l[j][1]);
                sp2h(ssp(acc1[2*j+1][0]+bB0), ssp(acc1[2*j+1][1]+bB1), a2h[j][2], a2l[j][2]);
                sp2h(ssp(acc1[2*j+1][2]+bB0), ssp(acc1[2*j+1][3]+bB1), a2h[j][3], a2l[j][3]);
            }
            // GEMM2 (reuse acc1)
            #pragma unroll
            for (int i=0;i<16;++i){acc1[i][0]=0;acc1[i][1]=0;acc1[i][2]=0;acc1[i][3]=0;}
            #pragma unroll
            for (int ks=0;ks<8;++ks)
                #pragma unroll
                for (int j=0;j<8;++j){
                    u32 bh[4]; u32 ba=loff+ks*(16*PIT)+j*32;
                    ldsm4t(bh,sWB+ba);
                    mma_hf(acc1[2*j],   a2h[ks],bh[0],bh[1]); mma_hf(acc1[2*j],   a2l[ks],bh[0],bh[1]);
                    mma_hf(acc1[2*j+1], a2h[ks],bh[2],bh[3]); mma_hf(acc1[2*j+1], a2l[ks],bh[2],bh[3]);
                }
            // epilogue
            const bool k0 = (s0 < 24) && (s0 != d);
            const bool k1 = (s1 < 24) && (s1 != d);
            float* agp = sagg2 + half*24*132 + d*132;
            #pragma unroll
            for (int j=0;j<8;++j){
                int cA=16*j+2*cp, cB=cA+8;
                float bA0=b2s[cA],bA1=b2s[cA+1],bB0=b2s[cB],bB1=b2s[cB+1];
                float v00=(acc1[2*j][0]+bA0)*xs[s0*132+cA];
                float v01=(acc1[2*j][1]+bA1)*xs[s0*132+cA+1];
                float v10=(acc1[2*j][2]+bA0)*xs[s1*132+cA];
                float v11=(acc1[2*j][3]+bA1)*xs[s1*132+cA+1];
                float w00=(acc1[2*j+1][0]+bB0)*xs[s0*132+cB];
                float w01=(acc1[2*j+1][1]+bB1)*xs[s0*132+cB+1];
                float w10=(acc1[2*j+1][2]+bB0)*xs[s1*132+cB];
                float w11=(acc1[2*j+1][3]+bB1)*xs[s1*132+cB+1];
                u32 h4[4],l4[4];
                sp2h(v00,v01,h4[0],l4[0]); sp2h(v10,v11,h4[1],l4[1]);
                sp2h(w00,w01,h4[2],l4[2]); sp2h(w10,w11,h4[3],l4[3]);
                u32* c = base + j*512;
                *(uint4*)(c+lane*4)     = make_uint4(h4[0],h4[1],h4[2],h4[3]);
                *(uint4*)(c+256+lane*4) = make_uint4(l4[0],l4[1],l4[2],l4[3]);
                float g0 = (k0?v00:0.f) + (k1?v10:0.f);
                float g1 = (k0?v01:0.f) + (k1?v11:0.f);
                float g2 = (k0?w00:0.f) + (k1?w10:0.f);
                float g3 = (k0?w01:0.f) + (k1?w11:0.f);
                g0 += __shfl_xor_sync(~0u,g0,4); g0 += __shfl_xor_sync(~0u,g0,8); g0 += __shfl_xor_sync(~0u,g0,16);
                g1 += __shfl_xor_sync(~0u,g1,4); g1 += __shfl_xor_sync(~0u,g1,8); g1 += __shfl_xor_sync(~0u,g1,16);
                g2 += __shfl_xor_sync(~0u,g2,4); g2 += __shfl_xor_sync(~0u,g2,8); g2 += __shfl_xor_sync(~0u,g2,16);
                g3 += __shfl_xor_sync(~0u,g3,4); g3 += __shfl_xor_sync(~0u,g3,8); g3 += __shfl_xor_sync(~0u,g3,16);
                if (lane < 4){
                    *(float2*)&agp[16*j + 2*lane]     = make_float2(g0, g1);
                    *(float2*)&agp[16*j + 8 + 2*lane] = make_float2(g2, g3);
                }
            }
        }
        __syncthreads();
        for (int i=tid;i<Aat*128;i+=NT){
            int dd=i>>7, c=i&127;
            sagg[dd*132+c] = sagg2[dd*132+c] + sagg2[24*132 + dd*132+c];
        }
        // ===== node phase =====
        for (int i=tid;i<2048;i+=NT){
            int k=i>>4, ch=i&15; u32 dof=k*PIT+ch*16;
            cpa16(sWA+dof, g_Wimg[3]+i*16);
            cpa16(sWB+dof, g_Wimg[4]+i*16);
        }
        CP_COMMIT; CP_WAIT0; __syncthreads();
        if (wid < 8){
            const int mb = wid & 1, cg = wid >> 1;
            float acc[4][4];
            #pragma unroll
            for (int i=0;i<4;++i){acc[i][0]=0;acc[i][1]=0;acc[i][2]=0;acc[i][3]=0;}
            gemm_sm(sagg, sWA, mb, cg, lane, loff, acc);
            int r0 = mb*16+q, r1 = r0+8;
            #pragma unroll
            for (int jb=0;jb<4;++jb){
                int c = (cg*2+(jb>>1))*16 + (jb&1)*8 + 2*cp;
                float b0v = bb[256+c], b1v = bb[256+c+1];
                *(float2*)&xs[r0*132+c] = make_float2(ssp(acc[jb][0]+b0v), ssp(acc[jb][1]+b1v));
                if (r1 < 24) *(float2*)&xs[r1*132+c] = make_float2(ssp(acc[jb][2]+b0v), ssp(acc[jb][3]+b1v));
            }
        }
        __syncthreads();
        if (wid < 8){
            const int mb = wid & 1, cg = wid >> 1;
            float acc[4][4];
            #pragma unroll
            for (int i=0;i<4;++i){acc[i][0]=0;acc[i][1]=0;acc[i][2]=0;acc[i][3]=0;}
            gemm_sm(xs, sWB, mb, cg, lane, loff, acc);
            int r0 = mb*16+q, r1 = r0+8;
            #pragma unroll
            for (int jb=0;jb<4;++jb){
                int c = (cg*2+(jb>>1))*16 + (jb&1)*8 + 2*cp;
                float b0v = bb[384+c], b1v = bb[384+c+1];
                float2 h0 = *(float2*)&hs[r0*132+c];
                h0.x += acc[jb][0]+b0v; h0.y += acc[jb][1]+b1v;
                *(float2*)&hs[r0*132+c] = h0;
                if (r1 < 24){
                    float2 h1 = *(float2*)&hs[r1*132+c];
                    h1.x += acc[jb][2]+b0v; h1.y += acc[jb][3]+b1v;
                    *(float2*)&hs[r1*132+c] = h1;
                }
            }
        }
        __syncthreads();
    }

    // ===== graph readout =====
    float* w1s = (float*)WA;
    for (int i=tid;i<2048;i+=NT) ((float4*)w1s)[i] = ((const float4*)gw1)[i];
    __syncthreads();
    float local = 0.f;
    for (int pos = tid; pos < Aat*64; pos += NT){
        int s = pos >> 6, c = pos & 63;
        float acc = gb1[c];
        #pragma unroll 16
        for (int k = 0; k < 128; ++k) acc += hs[s*132+k] * w1s[k*64+c];
        local += ssp(acc) * gw2[c];
    }
    float* red = sagg;
    red[tid] = local;
    if (tid < 128) red[NT + tid] = 0.f;
    __syncthreads();
    #pragma unroll
    for (int off = 256; off > 0; off >>= 1){
        if (tid < off) red[tid] += red[tid+off];
        __syncthreads();
    }
    if (tid == 0) out[m] = red[0] + (float)Aat * gb2[0];
}

extern "C" void kernel_launch(void* const* d_in, const int* in_sizes, int n_in,
                              void* d_out, int out_size)
{
    const int*   charges = (const int*)  d_in[0];
    const float* coords  = (const float*)d_in[1];
    const float* emb = (const float*)d_in[4];
    const float* nlw = (const float*)d_in[5];
    const float* ew1 = (const float*)d_in[6];
    const float* eb1 = (const float*)d_in[7];
    const float* ew2 = (const float*)d_in[8];
    const float* eb2 = (const float*)d_in[9];
    const float* nw1 = (const float*)d_in[10];
    const float* nb1 = (const float*)d_in[11];
    const float* nw2 = (const float*)d_in[12];
    const float* nb2 = (const float*)d_in[13];
    const float* gw1 = (const float*)d_in[14];
    const float* gb1 = (const float*)d_in[15];
    const float* gw2 = (const float*)d_in[16];
    const float* gb2 = (const float*)d_in[17];
    float* out = (float*)d_out;

    const int SMF = 2*IMG + (24*132 + 32*132 + 24*132 + 2*24*132 + 512)*4;  // 139264
    cudaFuncSetAttribute(k_fused, cudaFuncAttributeMaxDynamicSharedMemorySize, SMF);

    k_init <<<5, 128>>>(nlw, ew1, ew2, nw1, nw2);
    k_fused<<<Mmol, NT, SMF>>>(charges, coords, emb, eb1, eb2, nb1, nb2,
                               gw1, gb1, gw2, gb2, out);
}

// round 13
// speedup vs baseline: 2.0808x; 1.3656x over previous
#include <cuda_runtime.h>
#include <cuda_fp16.h>

typedef unsigned int u32; typedef unsigned long long u64;
#define Mmol 2048
#define Aat 24
#define PIT 272
#define IMG 34816
#define NT 384

// EA fragments per (m,d): 8 ks-chunks of 256 u32 [hi mb0 | hi mb1], fp16 pairs (hi only)
__device__ u32 g_EAf[(size_t)Mmol*24*2048];   // 302 MB
__device__ __align__(16) unsigned char g_Wimg[5][32768];   // fp16 weight images

__device__ __forceinline__ u32 smaddr(const void* p){
    u32 a; asm("{ .reg .u64 t; cvta.to.shared.u64 t, %1; cvt.u32.u64 %0, t; }" : "=r"(a) : "l"(p)); return a;
}
__device__ __forceinline__ float ssp(float x){
    return fmaxf(x, 0.f) + __logf(1.f + __expf(-fabsf(x))) - 0.6931471805599453f;
}
__device__ __forceinline__ void cpa16(u32 dst, const void* src){
    asm volatile("cp.async.cg.shared.global [%0], [%1], 16;" :: "r"(dst), "l"(src) : "memory");
}
#define CP_COMMIT asm volatile("cp.async.commit_group;" ::: "memory")
#define CP_WAIT0  asm volatile("cp.async.wait_group 0;"  ::: "memory")
__device__ __forceinline__ void ldsm4t(u32* r, u32 a){
    asm volatile("ldmatrix.sync.aligned.m8n8.x4.trans.shared.b16 {%0,%1,%2,%3}, [%4];"
        : "=r"(r[0]),"=r"(r[1]),"=r"(r[2]),"=r"(r[3]) : "r"(a));
}
__device__ __forceinline__ void mma_hf(float* d, const u32* a, u32 b0, u32 b1){
    asm volatile("mma.sync.aligned.m16n8k16.row.col.f32.f16.f16.f32 "
        "{%0,%1,%2,%3}, {%4,%5,%6,%7}, {%8,%9}, {%0,%1,%2,%3};"
        : "+f"(d[0]),"+f"(d[1]),"+f"(d[2]),"+f"(d[3])
        : "r"(a[0]),"r"(a[1]),"r"(a[2]),"r"(a[3]),"r"(b0),"r"(b1));
}
__device__ __forceinline__ u32 sph(float x, float y){
    __half2 hb = __floats2half2_rn(x, y); return *(u32*)&hb;
}
__device__ __forceinline__ void sp2h(float x, float y, u32& h, u32& l){
    __half2 hb = __floats2half2_rn(x, y);
    float2 hf = __half22float2(hb);
    __half2 lb = __floats2half2_rn(x - hf.x, y - hf.y);
    h = *(u32*)&hb; l = *(u32*)&lb;
}

__global__ void k_init(const float* nlw, const float* ew1, const float* ew2,
                       const float* nw1, const float* nw2){
    const float* srcs[5] = {nlw, ew1, ew2, nw1, nw2};
    const float* src = srcs[blockIdx.x];
    int n = threadIdx.x;
    for (int k = 0; k < 128; ++k)
        *(__half*)(g_Wimg[blockIdx.x] + k*256 + n*2) = __float2half_rn(src[k*128 + n]);
}

// M=32 x N=128 GEMM from fp32 smem rows, 2-term fp16 A (warps 0-7)
__device__ __forceinline__ void gemm_sm(const float* abuf, u32 bimg,
                                        int mb, int cg, int lane, u32 loff, float acc[4][4]){
    const int q = lane>>2, cp = lane&3;
    const int r0 = mb*16 + q, r1 = r0 + 8;
    const bool ok1 = (r1 < 24);
    #pragma unroll
    for (int ks=0; ks<8; ++ks){
        int kc = 16*ks + 2*cp;
        float2 v0 = *(const float2*)&abuf[r0*132+kc];
        float2 v1 = ok1 ? *(const float2*)&abuf[r1*132+kc] : make_float2(0.f,0.f);
        float2 v2 = *(const float2*)&abuf[r0*132+kc+8];
        float2 v3 = ok1 ? *(const float2*)&abuf[r1*132+kc+8] : make_float2(0.f,0.f);
        u32 ah[4], al[4];
        sp2h(v0.x,v0.y,ah[0],al[0]); sp2h(v1.x,v1.y,ah[1],al[1]);
        sp2h(v2.x,v2.y,ah[2],al[2]); sp2h(v3.x,v3.y,ah[3],al[3]);
        #pragma unroll
        for (int j=0;j<2;++j){
            u32 bh[4]; u32 ba = loff + ks*(16*PIT) + (cg*2+j)*32;
            ldsm4t(bh, bimg+ba);
            mma_hf(acc[2*j],   ah, bh[0], bh[1]);
            mma_hf(acc[2*j],   al, bh[0], bh[1]);
            mma_hf(acc[2*j+1], ah, bh[2], bh[3]);
            mma_hf(acc[2*j+1], al, bh[2], bh[3]);
        }
    }
}

__global__ void __launch_bounds__(NT,1) k_fused(
    const int* __restrict__ charges, const float* __restrict__ coords,
    const float* __restrict__ emb,
    const float* __restrict__ eb1, const float* __restrict__ eb2,
    const float* __restrict__ nb1, const float* __restrict__ nb2,
    const float* __restrict__ gw1, const float* __restrict__ gb1,
    const float* __restrict__ gw2, const float* __restrict__ gb2,
    float* __restrict__ out)
{
    extern __shared__ __align__(16) char sm[];
    char *WA = sm, *WB = sm+IMG;
    float* hs    = (float*)(sm + 2*IMG);   // 24x132
    float* xs    = hs + 24*132;            // 32x132 (rows 24-31 zero)
    float* sagg  = xs + 32*132;            // 24x132
    float* sagg2 = sagg + 24*132;          // 2 x 24x132
    float* bb    = sagg2 + 2*24*132;       // 512
    const int tid = threadIdx.x, m = blockIdx.x;
    const int wid = tid>>5, lane = tid&31, q = lane>>2, cp = lane&3;
    const u32 loff = (lane&15)*PIT + (lane>>4)*16;
    const u32 sWA = smaddr(WA), sWB = smaddr(WB);

    for (int i = tid; i < Aat*128; i += NT)
        hs[(i>>7)*132 + (i&127)] = emb[charges[m*Aat + (i>>7)]*128 + (i&127)];
    for (int i = tid; i < 8*132; i += NT) xs[24*132 + i] = 0.f;
    if (tid < 128){ bb[tid]=eb1[tid]; bb[128+tid]=eb2[tid]; bb[256+tid]=nb1[tid]; bb[384+tid]=nb2[tid]; }

    // RBF -> EA fragments (2 d's per warp), hi-only fp16
    {
        const float* cm = coords + (size_t)m*72;
        for (int i2 = 0; i2 < 2; ++i2){
            int d = wid + 12*i2;
            float ddx=cm[d*3], ddy=cm[d*3+1], ddz=cm[d*3+2];
            float dv[3];
            #pragma unroll
            for (int i=0;i<3;++i){
                int s = q + i*8;
                float ax=cm[s*3]-ddx, ay=cm[s*3+1]-ddy, az=cm[s*3+2]-ddz;
                dv[i] = sqrtf(ax*ax+ay*ay+az*az);
            }
            const float delta = 10.f/127.f, coeff = -0.5f/(delta*delta);
            u32* base = g_EAf + ((size_t)(m*24+d))*2048;
            #pragma unroll
            for (int ks=0; ks<8; ++ks){
                float c0 = (float)(16*ks + 2*cp);
                float v[3][4];
                #pragma unroll
                for (int i=0;i<3;++i)
                    #pragma unroll
                    for (int j=0;j<4;++j){
                        float od = dv[i] - delta*(c0 + (float)((j>>1)*8 + (j&1)));
                        v[i][j] = (fabsf(od) < 1.2f) ? __expf(coeff*od*od) : 0.f;
                    }
                u32* c = base + ks*256;
                *(uint4*)(c + lane*4) = make_uint4(
                    sph(v[0][0],v[0][1]), sph(v[1][0],v[1][1]),
                    sph(v[0][2],v[0][3]), sph(v[1][2],v[1][3]));
                *(uint4*)(c + 128 + lane*4) = make_uint4(
                    sph(v[2][0],v[2][1]), 0u,
                    sph(v[2][2],v[2][3]), 0u);
            }
        }
    }

    const float* b1s = bb;
    const float* b2s = bb + 128;

    for (int layer = 0; layer < 4; ++layer){
        // ===== x = h @ nlw =====
        for (int i=tid;i<2048;i+=NT){
            int k=i>>4, ch=i&15;
            cpa16(sWA + k*PIT+ch*16, g_Wimg[0]+i*16);
        }
        CP_COMMIT; CP_WAIT0; __syncthreads();
        if (wid < 8){
            const int mb = wid & 1, cg = wid >> 1;
            float acc[4][4];
            #pragma unroll
            for (int i=0;i<4;++i){acc[i][0]=0;acc[i][1]=0;acc[i][2]=0;acc[i][3]=0;}
            gemm_sm(hs, sWA, mb, cg, lane, loff, acc);
            int r0 = mb*16+q, r1 = r0+8;
            #pragma unroll
            for (int jb=0;jb<4;++jb){
                int c = (cg*2+(jb>>1))*16 + (jb&1)*8 + 2*cp;
                *(float2*)&xs[r0*132+c] = make_float2(acc[jb][0], acc[jb][1]);
                if (r1 < 24) *(float2*)&xs[r1*132+c] = make_float2(acc[jb][2], acc[jb][3]);
            }
        }
        __syncthreads();
        // ===== edge phase: 48 half-tasks, 12 warps x 4 passes =====
        for (int i=tid;i<2048;i+=NT){
            int k=i>>4, ch=i&15; u32 dof=k*PIT+ch*16;
            cpa16(sWA+dof, g_Wimg[1]+i*16);
            cpa16(sWB+dof, g_Wimg[2]+i*16);
        }
        CP_COMMIT; CP_WAIT0; __syncthreads();
        for (int pass=0; pass<4; ++pass){
            const int task = pass*12 + wid;
            const int d = task >> 1, half = task & 1;
            u32* base = g_EAf + ((size_t)(m*24+d))*2048 + half*128;
            const int s0 = half*16 + q, s1 = s0 + 8;

            // GEMM1: A = EA hi fragments (L2-hot), 1-term fp16
            float acc1[16][4];
            #pragma unroll
            for (int i=0;i<16;++i){acc1[i][0]=0;acc1[i][1]=0;acc1[i][2]=0;acc1[i][3]=0;}
            uint4 H = *(const uint4*)(base + lane*4);
            #pragma unroll
            for (int ks=0;ks<8;++ks){
                uint4 nH;
                if (ks<7) nH = *(const uint4*)(base + (ks+1)*256 + lane*4);
                u32 ah[4]={H.x,H.y,H.z,H.w};
                #pragma unroll
                for (int j=0;j<8;++j){
                    u32 bh[4]; u32 ba=loff+ks*(16*PIT)+j*32;
                    ldsm4t(bh,sWA+ba);
                    mma_hf(acc1[2*j],   ah,bh[0],bh[1]);
                    mma_hf(acc1[2*j+1], ah,bh[2],bh[3]);
                }
                if (ks<7) H = nH;
            }
            // mid = ssp(acc1+b1) -> A2 fragments (hi-only fp16)
            u32 a2h[8][4];
            #pragma unroll
            for (int j=0;j<8;++j){
                int c0=16*j+2*cp;
                float bA0=b1s[c0], bA1=b1s[c0+1], bB0=b1s[c0+8], bB1=b1s[c0+9];
                a2h[j][0] = sph(ssp(acc1[2*j][0]+bA0),   ssp(acc1[2*j][1]+bA1));
                a2h[j][1] = sph(ssp(acc1[2*j][2]+bA0),   ssp(acc1[2*j][3]+bA1));
                a2h[j][2] = sph(ssp(acc1[2*j+1][0]+bB0), ssp(acc1[2*j+1][1]+bB1));
                a2h[j][3] = sph(ssp(acc1[2*j+1][2]+bB0), ssp(acc1[2*j+1][3]+bB1));
            }
            // GEMM2 (reuse acc1), 1-term fp16
            #pragma unroll
            for (int i=0;i<16;++i){acc1[i][0]=0;acc1[i][1]=0;acc1[i][2]=0;acc1[i][3]=0;}
            #pragma unroll
            for (int ks=0;ks<8;++ks)
                #pragma unroll
                for (int j=0;j<8;++j){
                    u32 bh[4]; u32 ba=loff+ks*(16*PIT)+j*32;
                    ldsm4t(bh,sWB+ba);
                    mma_hf(acc1[2*j],   a2h[ks],bh[0],bh[1]);
                    mma_hf(acc1[2*j+1], a2h[ks],bh[2],bh[3]);
                }
            // epilogue
            const bool k0 = (s0 < 24) && (s0 != d);
            const bool k1 = (s1 < 24) && (s1 != d);
            float* agp = sagg2 + half*24*132 + d*132;
            #pragma unroll
            for (int j=0;j<8;++j){
                int cA=16*j+2*cp, cB=cA+8;
                float bA0=b2s[cA],bA1=b2s[cA+1],bB0=b2s[cB],bB1=b2s[cB+1];
                float v00=(acc1[2*j][0]+bA0)*xs[s0*132+cA];
                float v01=(acc1[2*j][1]+bA1)*xs[s0*132+cA+1];
                float v10=(acc1[2*j][2]+bA0)*xs[s1*132+cA];
                float v11=(acc1[2*j][3]+bA1)*xs[s1*132+cA+1];
                float w00=(acc1[2*j+1][0]+bB0)*xs[s0*132+cB];
                float w01=(acc1[2*j+1][1]+bB1)*xs[s0*132+cB+1];
                float w10=(acc1[2*j+1][2]+bB0)*xs[s1*132+cB];
                float w11=(acc1[2*j+1][3]+bB1)*xs[s1*132+cB+1];
                *(uint4*)(base + j*256 + lane*4) = make_uint4(
                    sph(v00,v01), sph(v10,v11), sph(w00,w01), sph(w10,w11));
                float g0 = (k0?v00:0.f) + (k1?v10:0.f);
                float g1 = (k0?v01:0.f) + (k1?v11:0.f);
                float g2 = (k0?w00:0.f) + (k1?w10:0.f);
                float g3 = (k0?w01:0.f) + (k1?w11:0.f);
                g0 += __shfl_xor_sync(~0u,g0,4); g0 += __shfl_xor_sync(~0u,g0,8); g0 += __shfl_xor_sync(~0u,g0,16);
                g1 += __shfl_xor_sync(~0u,g1,4); g1 += __shfl_xor_sync(~0u,g1,8); g1 += __shfl_xor_sync(~0u,g1,16);
                g2 += __shfl_xor_sync(~0u,g2,4); g2 += __shfl_xor_sync(~0u,g2,8); g2 += __shfl_xor_sync(~0u,g2,16);
                g3 += __shfl_xor_sync(~0u,g3,4); g3 += __shfl_xor_sync(~0u,g3,8); g3 += __shfl_xor_sync(~0u,g3,16);
                if (lane < 4){
                    *(float2*)&agp[16*j + 2*lane]     = make_float2(g0, g1);
                    *(float2*)&agp[16*j + 8 + 2*lane] = make_float2(g2, g3);
                }
            }
        }
        __syncthreads();
        for (int i=tid;i<Aat*128;i+=NT){
            int dd=i>>7, c=i&127;
            sagg[dd*132+c] = sagg2[dd*132+c] + sagg2[24*132 + dd*132+c];
        }
        // ===== node phase =====
        for (int i=tid;i<2048;i+=NT){
            int k=i>>4, ch=i&15; u32 dof=k*PIT+ch*16;
            cpa16(sWA+dof, g_Wimg[3]+i*16);
            cpa16(sWB+dof, g_Wimg[4]+i*16);
        }
        CP_COMMIT; CP_WAIT0; __syncthreads();
        if (wid < 8){
            const int mb = wid & 1, cg = wid >> 1;
            float acc[4][4];
            #pragma unroll
            for (int i=0;i<4;++i){acc[i][0]=0;acc[i][1]=0;acc[i][2]=0;acc[i][3]=0;}
            gemm_sm(sagg, sWA, mb, cg, lane, loff, acc);
            int r0 = mb*16+q, r1 = r0+8;
            #pragma unroll
            for (int jb=0;jb<4;++jb){
                int c = (cg*2+(jb>>1))*16 + (jb&1)*8 + 2*cp;
                float b0v = bb[256+c], b1v = bb[256+c+1];
                *(float2*)&xs[r0*132+c] = make_float2(ssp(acc[jb][0]+b0v), ssp(acc[jb][1]+b1v));
                if (r1 < 24) *(float2*)&xs[r1*132+c] = make_float2(ssp(acc[jb][2]+b0v), ssp(acc[jb][3]+b1v));
            }
        }
        __syncthreads();
        if (wid < 8){
            const int mb = wid & 1, cg = wid >> 1;
            float acc[4][4];
            #pragma unroll
            for (int i=0;i<4;++i){acc[i][0]=0;acc[i][1]=0;acc[i][2]=0;acc[i][3]=0;}
            gemm_sm(xs, sWB, mb, cg, lane, loff, acc);
            int r0 = mb*16+q, r1 = r0+8;
            #pragma unroll
            for (int jb=0;jb<4;++jb){
                int c = (cg*2+(jb>>1))*16 + (jb&1)*8 + 2*cp;
                float b0v = bb[384+c], b1v = bb[384+c+1];
                float2 h0 = *(float2*)&hs[r0*132+c];
                h0.x += acc[jb][0]+b0v; h0.y += acc[jb][1]+b1v;
                *(float2*)&hs[r0*132+c] = h0;
                if (r1 < 24){
                    float2 h1 = *(float2*)&hs[r1*132+c];
                    h1.x += acc[jb][2]+b0v; h1.y += acc[jb][3]+b1v;
                    *(float2*)&hs[r1*132+c] = h1;
                }
            }
        }
        __syncthreads();
    }

    // ===== graph readout =====
    float* w1s = (float*)WA;
    for (int i=tid;i<2048;i+=NT) ((float4*)w1s)[i] = ((const float4*)gw1)[i];
    __syncthreads();
    float local = 0.f;
    for (int pos = tid; pos < Aat*64; pos += NT){
        int s = pos >> 6, c = pos & 63;
        float acc = gb1[c];
        #pragma unroll 16
        for (int k = 0; k < 128; ++k) acc += hs[s*132+k] * w1s[k*64+c];
        local += ssp(acc) * gw2[c];
    }
    float* red = sagg;
    red[tid] = local;
    if (tid < 128) red[NT + tid] = 0.f;
    __syncthreads();
    #pragma unroll
    for (int off = 256; off > 0; off >>= 1){
        if (tid < off) red[tid] += red[tid+off];
        __syncthreads();
    }
    if (tid == 0) out[m] = red[0] + (float)Aat * gb2[0];
}

extern "C" void kernel_launch(void* const* d_in, const int* in_sizes, int n_in,
                              void* d_out, int out_size)
{
    const int*   charges = (const int*)  d_in[0];
    const float* coords  = (const float*)d_in[1];
    const float* emb = (const float*)d_in[4];
    const float* nlw = (const float*)d_in[5];
    const float* ew1 = (const float*)d_in[6];
    const float* eb1 = (const float*)d_in[7];
    const float* ew2 = (const float*)d_in[8];
    const float* eb2 = (const float*)d_in[9];
    const float* nw1 = (const float*)d_in[10];
    const float* nb1 = (const float*)d_in[11];
    const float* nw2 = (const float*)d_in[12];
    const float* nb2 = (const float*)d_in[13];
    const float* gw1 = (const float*)d_in[14];
    const float* gb1 = (const float*)d_in[15];
    const float* gw2 = (const float*)d_in[16];
    const float* gb2 = (const float*)d_in[17];
    float* out = (float*)d_out;

    const int SMF = 2*IMG + (24*132 + 32*132 + 24*132 + 2*24*132 + 512)*4;  // 139264
    cudaFuncSetAttribute(k_fused, cudaFuncAttributeMaxDynamicSharedMemorySize, SMF);

    k_init <<<5, 128>>>(nlw, ew1, ew2, nw1, nw2);
    k_fused<<<Mmol, NT, SMF>>>(charges, coords, emb, eb1, eb2, nb1, nb2,
                               gw1, gb1, gw2, gb2, out);
}

// round 14
// speedup vs baseline: 2.1285x; 1.0229x over previous
#include <cuda_runtime.h>
#include <cuda_fp16.h>

typedef unsigned int u32; typedef unsigned long long u64;
#define Mmol 2048
#define Aat 24
#define PIT 272
#define IMG 34816
#define NT 384

// EA fragments per (m,d): 8 ks-chunks of 256 u32 [hi mb0 | hi mb1], fp16 pairs
__device__ u32 g_EAf[(size_t)Mmol*24*2048];   // 302 MB
__device__ __align__(16) unsigned char g_Wimg[5][32768];   // fp16 weight images

__device__ __forceinline__ u32 smaddr(const void* p){
    u32 a; asm("{ .reg .u64 t; cvta.to.shared.u64 t, %1; cvt.u32.u64 %0, t; }" : "=r"(a) : "l"(p)); return a;
}
__device__ __forceinline__ float ssp(float x){
    return fmaxf(x, 0.f) + __logf(1.f + __expf(-fabsf(x))) - 0.6931471805599453f;
}
__device__ __forceinline__ void cpa16(u32 dst, const void* src){
    asm volatile("cp.async.cg.shared.global [%0], [%1], 16;" :: "r"(dst), "l"(src) : "memory");
}
#define CP_COMMIT asm volatile("cp.async.commit_group;" ::: "memory")
#define CP_WAIT0  asm volatile("cp.async.wait_group 0;"  ::: "memory")
__device__ __forceinline__ void ldsm4t(u32* r, u32 a){
    asm volatile("ldmatrix.sync.aligned.m8n8.x4.trans.shared.b16 {%0,%1,%2,%3}, [%4];"
        : "=r"(r[0]),"=r"(r[1]),"=r"(r[2]),"=r"(r[3]) : "r"(a));
}
__device__ __forceinline__ void mma_hf(float* d, const u32* a, u32 b0, u32 b1){
    asm volatile("mma.sync.aligned.m16n8k16.row.col.f32.f16.f16.f32 "
        "{%0,%1,%2,%3}, {%4,%5,%6,%7}, {%8,%9}, {%0,%1,%2,%3};"
        : "+f"(d[0]),"+f"(d[1]),"+f"(d[2]),"+f"(d[3])
        : "r"(a[0]),"r"(a[1]),"r"(a[2]),"r"(a[3]),"r"(b0),"r"(b1));
}
__device__ __forceinline__ u32 sph(float x, float y){
    __half2 hb = __floats2half2_rn(x, y); return *(u32*)&hb;
}
__device__ __forceinline__ void sp2h(float x, float y, u32& h, u32& l){
    __half2 hb = __floats2half2_rn(x, y);
    float2 hf = __half22float2(hb);
    __half2 lb = __floats2half2_rn(x - hf.x, y - hf.y);
    h = *(u32*)&hb; l = *(u32*)&lb;
}

__global__ void k_init(const float* nlw, const float* ew1, const float* ew2,
                       const float* nw1, const float* nw2){
    const float* srcs[5] = {nlw, ew1, ew2, nw1, nw2};
    const float* src = srcs[blockIdx.x];
    int n = threadIdx.x;
    for (int k = 0; k < 128; ++k)
        *(__half*)(g_Wimg[blockIdx.x] + k*256 + n*2) = __float2half_rn(src[k*128 + n]);
}

// M=32 x N=128 GEMM from fp32 smem rows, 2-term fp16 A (warps 0-7)
__device__ __forceinline__ void gemm_sm(const float* abuf, u32 bimg,
                                        int mb, int cg, int lane, u32 loff, float acc[4][4]){
    const int q = lane>>2, cp = lane&3;
    const int r0 = mb*16 + q, r1 = r0 + 8;
    const bool ok1 = (r1 < 24);
    #pragma unroll
    for (int ks=0; ks<8; ++ks){
        int kc = 16*ks + 2*cp;
        float2 v0 = *(const float2*)&abuf[r0*132+kc];
        float2 v1 = ok1 ? *(const float2*)&abuf[r1*132+kc] : make_float2(0.f,0.f);
        float2 v2 = *(const float2*)&abuf[r0*132+kc+8];
        float2 v3 = ok1 ? *(const float2*)&abuf[r1*132+kc+8] : make_float2(0.f,0.f);
        u32 ah[4], al[4];
        sp2h(v0.x,v0.y,ah[0],al[0]); sp2h(v1.x,v1.y,ah[1],al[1]);
        sp2h(v2.x,v2.y,ah[2],al[2]); sp2h(v3.x,v3.y,ah[3],al[3]);
        #pragma unroll
        for (int j=0;j<2;++j){
            u32 bh[4]; u32 ba = loff + ks*(16*PIT) + (cg*2+j)*32;
            ldsm4t(bh, bimg+ba);
            mma_hf(acc[2*j],   ah, bh[0], bh[1]);
            mma_hf(acc[2*j],   al, bh[0], bh[1]);
            mma_hf(acc[2*j+1], ah, bh[2], bh[3]);
            mma_hf(acc[2*j+1], al, bh[2], bh[3]);
        }
    }
}

__global__ void __launch_bounds__(NT,1) k_fused(
    const int* __restrict__ charges, const float* __restrict__ coords,
    const float* __restrict__ emb,
    const float* __restrict__ eb1, const float* __restrict__ eb2,
    const float* __restrict__ nb1, const float* __restrict__ nb2,
    const float* __restrict__ gw1, const float* __restrict__ gb1,
    const float* __restrict__ gw2, const float* __restrict__ gb2,
    float* __restrict__ out)
{
    extern __shared__ __align__(16) char sm[];
    char *WA = sm, *WB = sm+IMG;
    float* hs    = (float*)(sm + 2*IMG);   // 24x132
    float* xs    = hs + 24*132;            // 32x132 (rows 24-31 zero)
    float* sagg  = xs + 32*132;            // 24x132
    float* bb    = sagg + 24*132;          // 512
    const int tid = threadIdx.x, m = blockIdx.x;
    const int wid = tid>>5, lane = tid&31, q = lane>>2, cp = lane&3;
    const u32 loff = (lane&15)*PIT + (lane>>4)*16;
    const u32 sWA = smaddr(WA), sWB = smaddr(WB);

    for (int i = tid; i < Aat*128; i += NT)
        hs[(i>>7)*132 + (i&127)] = emb[charges[m*Aat + (i>>7)]*128 + (i&127)];
    for (int i = tid; i < 8*132; i += NT) xs[24*132 + i] = 0.f;
    if (tid < 128){ bb[tid]=eb1[tid]; bb[128+tid]=eb2[tid]; bb[256+tid]=nb1[tid]; bb[384+tid]=nb2[tid]; }

    // RBF -> EA fragments (2 d's per warp), hi-only fp16
    {
        const float* cm = coords + (size_t)m*72;
        for (int i2 = 0; i2 < 2; ++i2){
            int d = wid + 12*i2;
            float ddx=cm[d*3], ddy=cm[d*3+1], ddz=cm[d*3+2];
            float dv[3];
            #pragma unroll
            for (int i=0;i<3;++i){
                int s = q + i*8;
                float ax=cm[s*3]-ddx, ay=cm[s*3+1]-ddy, az=cm[s*3+2]-ddz;
                dv[i] = sqrtf(ax*ax+ay*ay+az*az);
            }
            const float delta = 10.f/127.f, coeff = -0.5f/(delta*delta);
            u32* base = g_EAf + ((size_t)(m*24+d))*2048;
            #pragma unroll
            for (int ks=0; ks<8; ++ks){
                float c0 = (float)(16*ks + 2*cp);
                float v[3][4];
                #pragma unroll
                for (int i=0;i<3;++i)
                    #pragma unroll
                    for (int j=0;j<4;++j){
                        float od = dv[i] - delta*(c0 + (float)((j>>1)*8 + (j&1)));
                        v[i][j] = (fabsf(od) < 1.2f) ? __expf(coeff*od*od) : 0.f;
                    }
                u32* c = base + ks*256;
                *(uint4*)(c + lane*4) = make_uint4(
                    sph(v[0][0],v[0][1]), sph(v[1][0],v[1][1]),
                    sph(v[0][2],v[0][3]), sph(v[1][2],v[1][3]));
                *(uint4*)(c + 128 + lane*4) = make_uint4(
                    sph(v[2][0],v[2][1]), 0u,
                    sph(v[2][2],v[2][3]), 0u);
            }
        }
    }

    const float* b1s = bb;
    const float* b2s = bb + 128;

    for (int layer = 0; layer < 4; ++layer){
        // ===== x = h @ nlw =====
        for (int i=tid;i<2048;i+=NT){
            int k=i>>4, ch=i&15;
            cpa16(sWA + k*PIT+ch*16, g_Wimg[0]+i*16);
        }
        CP_COMMIT; CP_WAIT0; __syncthreads();
        if (wid < 8){
            const int mb = wid & 1, cg = wid >> 1;
            float acc[4][4];
            #pragma unroll
            for (int i=0;i<4;++i){acc[i][0]=0;acc[i][1]=0;acc[i][2]=0;acc[i][3]=0;}
            gemm_sm(hs, sWA, mb, cg, lane, loff, acc);
            int r0 = mb*16+q, r1 = r0+8;
            #pragma unroll
            for (int jb=0;jb<4;++jb){
                int c = (cg*2+(jb>>1))*16 + (jb&1)*8 + 2*cp;
                *(float2*)&xs[r0*132+c] = make_float2(acc[jb][0], acc[jb][1]);
                if (r1 < 24) *(float2*)&xs[r1*132+c] = make_float2(acc[jb][2], acc[jb][3]);
            }
        }
        __syncthreads();
        // ===== edge phase: 24 d's, 12 warps x 2 passes, M=32 per warp =====
        for (int i=tid;i<2048;i+=NT){
            int k=i>>4, ch=i&15; u32 dof=k*PIT+ch*16;
            cpa16(sWA+dof, g_Wimg[1]+i*16);
            cpa16(sWB+dof, g_Wimg[2]+i*16);
        }
        CP_COMMIT; CP_WAIT0; __syncthreads();
        for (int pass=0; pass<2; ++pass){
            const int d = pass*12 + wid;
            u32* base = g_EAf + ((size_t)(m*24+d))*2048;

            // ---- GEMM1 in two N-halves, 1-term fp16, M=32 ----
            u32 a2h[2][8][4];
            #pragma unroll
            for (int half=0; half<2; ++half){
                float acc1[2][8][4];
                #pragma unroll
                for (int i=0;i<8;++i){
                    acc1[0][i][0]=0;acc1[0][i][1]=0;acc1[0][i][2]=0;acc1[0][i][3]=0;
                    acc1[1][i][0]=0;acc1[1][i][1]=0;acc1[1][i][2]=0;acc1[1][i][3]=0;
                }
                #pragma unroll
                for (int ks=0;ks<8;++ks){
                    uint4 H0 = *(const uint4*)(base + ks*256 + lane*4);
                    uint4 H1 = *(const uint4*)(base + ks*256 + 128 + lane*4);
                    u32 ah0[4]={H0.x,H0.y,H0.z,H0.w}, ah1[4]={H1.x,H1.y,H1.z,H1.w};
                    #pragma unroll
                    for (int j=0;j<4;++j){
                        int jj = half*4 + j;
                        u32 bh[4]; u32 ba=loff+ks*(16*PIT)+jj*32;
                        ldsm4t(bh,sWA+ba);
                        mma_hf(acc1[0][2*j],   ah0,bh[0],bh[1]);
                        mma_hf(acc1[0][2*j+1], ah0,bh[2],bh[3]);
                        mma_hf(acc1[1][2*j],   ah1,bh[0],bh[1]);
                        mma_hf(acc1[1][2*j+1], ah1,bh[2],bh[3]);
                    }
                }
                #pragma unroll
                for (int mb=0;mb<2;++mb)
                    #pragma unroll
                    for (int j=0;j<4;++j){
                        int jj = half*4 + j;
                        int c0 = 16*jj + 2*cp;
                        float bA0=b1s[c0], bA1=b1s[c0+1], bB0=b1s[c0+8], bB1=b1s[c0+9];
                        a2h[mb][jj][0] = sph(ssp(acc1[mb][2*j][0]+bA0),   ssp(acc1[mb][2*j][1]+bA1));
                        a2h[mb][jj][1] = sph(ssp(acc1[mb][2*j][2]+bA0),   ssp(acc1[mb][2*j][3]+bA1));
                        a2h[mb][jj][2] = sph(ssp(acc1[mb][2*j+1][0]+bB0), ssp(acc1[mb][2*j+1][1]+bB1));
                        a2h[mb][jj][3] = sph(ssp(acc1[mb][2*j+1][2]+bB0), ssp(acc1[mb][2*j+1][3]+bB1));
                    }
            }
            // ---- GEMM2 in two N-halves + fused epilogue ----
            #pragma unroll
            for (int hf=0; hf<2; ++hf){
                float acc2[2][8][4];
                #pragma unroll
                for (int i=0;i<8;++i){
                    acc2[0][i][0]=0;acc2[0][i][1]=0;acc2[0][i][2]=0;acc2[0][i][3]=0;
                    acc2[1][i][0]=0;acc2[1][i][1]=0;acc2[1][i][2]=0;acc2[1][i][3]=0;
                }
                #pragma unroll
                for (int ks=0;ks<8;++ks)
                    #pragma unroll
                    for (int j=0;j<4;++j){
                        u32 bh[4]; u32 ba=loff+ks*(16*PIT)+(hf*4+j)*32;
                        ldsm4t(bh,sWB+ba);
                        mma_hf(acc2[0][2*j],   a2h[0][ks],bh[0],bh[1]);
                        mma_hf(acc2[0][2*j+1], a2h[0][ks],bh[2],bh[3]);
                        mma_hf(acc2[1][2*j],   a2h[1][ks],bh[0],bh[1]);
                        mma_hf(acc2[1][2*j+1], a2h[1][ks],bh[2],bh[3]);
                    }
                float wag[4][4];
                #pragma unroll
                for (int j=0;j<4;++j){wag[j][0]=0;wag[j][1]=0;wag[j][2]=0;wag[j][3]=0;}
                #pragma unroll
                for (int mb=0;mb<2;++mb){
                    int s0=mb*16+q, s1=s0+8;
                    bool k0=(s0<24)&&(s0!=d), k1=(s1<24)&&(s1!=d);
                    #pragma unroll
                    for (int j=0;j<4;++j){
                        int cA=hf*64+16*j+2*cp, cB=cA+8;
                        float bA0=b2s[cA],bA1=b2s[cA+1],bB0=b2s[cB],bB1=b2s[cB+1];
                        float v00=(acc2[mb][2*j][0]+bA0)*xs[s0*132+cA];
                        float v01=(acc2[mb][2*j][1]+bA1)*xs[s0*132+cA+1];
                        float v10=(acc2[mb][2*j][2]+bA0)*xs[s1*132+cA];
                        float v11=(acc2[mb][2*j][3]+bA1)*xs[s1*132+cA+1];
                        float w00=(acc2[mb][2*j+1][0]+bB0)*xs[s0*132+cB];
                        float w01=(acc2[mb][2*j+1][1]+bB1)*xs[s0*132+cB+1];
                        float w10=(acc2[mb][2*j+1][2]+bB0)*xs[s1*132+cB];
                        float w11=(acc2[mb][2*j+1][3]+bB1)*xs[s1*132+cB+1];
                        *(uint4*)(base + (hf*4+j)*256 + mb*128 + lane*4) = make_uint4(
                            sph(v00,v01), sph(v10,v11), sph(w00,w01), sph(w10,w11));
                        if(k0){ wag[j][0]+=v00; wag[j][1]+=v01; wag[j][2]+=w00; wag[j][3]+=w01; }
                        if(k1){ wag[j][0]+=v10; wag[j][1]+=v11; wag[j][2]+=w10; wag[j][3]+=w11; }
                    }
                }
                #pragma unroll
                for (int j=0;j<4;++j){
                    #pragma unroll
                    for (int u2=0;u2<4;++u2){
                        float tt=wag[j][u2];
                        tt += __shfl_xor_sync(~0u,tt,4); tt += __shfl_xor_sync(~0u,tt,8); tt += __shfl_xor_sync(~0u,tt,16);
                        wag[j][u2]=tt;
                    }
                    if (lane<4){
                        int cA=hf*64+16*j+2*lane;
                        *(float2*)&sagg[d*132+cA]   = make_float2(wag[j][0],wag[j][1]);
                        *(float2*)&sagg[d*132+cA+8] = make_float2(wag[j][2],wag[j][3]);
                    }
                }
            }
        }
        __syncthreads();
        // ===== node phase =====
        for (int i=tid;i<2048;i+=NT){
            int k=i>>4, ch=i&15; u32 dof=k*PIT+ch*16;
            cpa16(sWA+dof, g_Wimg[3]+i*16);
            cpa16(sWB+dof, g_Wimg[4]+i*16);
        }
        CP_COMMIT; CP_WAIT0; __syncthreads();
        if (wid < 8){
            const int mb = wid & 1, cg = wid >> 1;
            float acc[4][4];
            #pragma unroll
            for (int i=0;i<4;++i){acc[i][0]=0;acc[i][1]=0;acc[i][2]=0;acc[i][3]=0;}
            gemm_sm(sagg, sWA, mb, cg, lane, loff, acc);
            int r0 = mb*16+q, r1 = r0+8;
            #pragma unroll
            for (int jb=0;jb<4;++jb){
                int c = (cg*2+(jb>>1))*16 + (jb&1)*8 + 2*cp;
                float b0v = bb[256+c], b1v = bb[256+c+1];
                *(float2*)&xs[r0*132+c] = make_float2(ssp(acc[jb][0]+b0v), ssp(acc[jb][1]+b1v));
                if (r1 < 24) *(float2*)&xs[r1*132+c] = make_float2(ssp(acc[jb][2]+b0v), ssp(acc[jb][3]+b1v));
            }
        }
        __syncthreads();
        if (wid < 8){
            const int mb = wid & 1, cg = wid >> 1;
            float acc[4][4];
            #pragma unroll
            for (int i=0;i<4;++i){acc[i][0]=0;acc[i][1]=0;acc[i][2]=0;acc[i][3]=0;}
            gemm_sm(xs, sWB, mb, cg, lane, loff, acc);
            int r0 = mb*16+q, r1 = r0+8;
            #pragma unroll
            for (int jb=0;jb<4;++jb){
                int c = (cg*2+(jb>>1))*16 + (jb&1)*8 + 2*cp;
                float b0v = bb[384+c], b1v = bb[384+c+1];
                float2 h0 = *(float2*)&hs[r0*132+c];
                h0.x += acc[jb][0]+b0v; h0.y += acc[jb][1]+b1v;
                *(float2*)&hs[r0*132+c] = h0;
                if (r1 < 24){
                    float2 h1 = *(float2*)&hs[r1*132+c];
                    h1.x += acc[jb][2]+b0v; h1.y += acc[jb][3]+b1v;
                    *(float2*)&hs[r1*132+c] = h1;
                }
            }
        }
        __syncthreads();
    }

    // ===== graph readout =====
    float* w1s = (float*)WA;
    for (int i=tid;i<2048;i+=NT) ((float4*)w1s)[i] = ((const float4*)gw1)[i];
    __syncthreads();
    float local = 0.f;
    for (int pos = tid; pos < Aat*64; pos += NT){
        int s = pos >> 6, c = pos & 63;
        float acc = gb1[c];
        #pragma unroll 16
        for (int k = 0; k < 128; ++k) acc += hs[s*132+k] * w1s[k*64+c];
        local += ssp(acc) * gw2[c];
    }
    float* red = sagg;
    red[tid] = local;
    if (tid < 128) red[NT + tid] = 0.f;
    __syncthreads();
    #pragma unroll
    for (int off = 256; off > 0; off >>= 1){
        if (tid < off) red[tid] += red[tid+off];
        __syncthreads();
    }
    if (tid == 0) out[m] = red[0] + (float)Aat * gb2[0];
}

extern "C" void kernel_launch(void* const* d_in, const int* in_sizes, int n_in,
                              void* d_out, int out_size)
{
    const int*   charges = (const int*)  d_in[0];
    const float* coords  = (const float*)d_in[1];
    const float* emb = (const float*)d_in[4];
    const float* nlw = (const float*)d_in[5];
    const float* ew1 = (const float*)d_in[6];
    const float* eb1 = (const float*)d_in[7];
    const float* ew2 = (const float*)d_in[8];
    const float* eb2 = (const float*)d_in[9];
    const float* nw1 = (const float*)d_in[10];
    const float* nb1 = (const float*)d_in[11];
    const float* nw2 = (const float*)d_in[12];
    const float* nb2 = (const float*)d_in[13];
    const float* gw1 = (const float*)d_in[14];
    const float* gb1 = (const float*)d_in[15];
    const float* gw2 = (const float*)d_in[16];
    const float* gb2 = (const float*)d_in[17];
    float* out = (float*)d_out;

    const int SMF = 2*IMG + (24*132 + 32*132 + 24*132 + 512)*4;  // 113920
    cudaFuncSetAttribute(k_fused, cudaFuncAttributeMaxDynamicSharedMemorySize, SMF);

    k_init <<<5, 128>>>(nlw, ew1, ew2, nw1, nw2);
    k_fused<<<Mmol, NT, SMF>>>(charges, coords, emb, eb1, eb2, nb1, nb2,
                               gw1, gb1, gw2, gb2, out);
}

// round 15
// speedup vs baseline: 2.2429x; 1.0537x over previous
#include <cuda_runtime.h>
#include <cuda_fp16.h>

typedef unsigned int u32; typedef unsigned long long u64;
#define Mmol 2048
#define Aat 24
#define PIT 272
#define IMG 34816
#define NT 384

// EA fragments per (m,d): 8 ks-chunks of 256 u32 [hi mb0 | hi mb1], fp16 pairs
__device__ u32 g_EAf[(size_t)Mmol*24*2048];   // 302 MB
__device__ __align__(16) unsigned char g_Wimg[5][32768];   // fp16 weight images

__device__ __forceinline__ u32 smaddr(const void* p){
    u32 a; asm("{ .reg .u64 t; cvta.to.shared.u64 t, %1; cvt.u32.u64 %0, t; }" : "=r"(a) : "l"(p)); return a;
}
__device__ __forceinline__ float ssp(float x){
    return fmaxf(x, 0.f) + __logf(1.f + __expf(-fabsf(x))) - 0.6931471805599453f;
}
__device__ __forceinline__ void cpa16(u32 dst, const void* src){
    asm volatile("cp.async.cg.shared.global [%0], [%1], 16;" :: "r"(dst), "l"(src) : "memory");
}
#define CP_COMMIT asm volatile("cp.async.commit_group;" ::: "memory")
#define CP_WAIT0  asm volatile("cp.async.wait_group 0;"  ::: "memory")
__device__ __forceinline__ void ldsm4t(u32* r, u32 a){
    asm volatile("ldmatrix.sync.aligned.m8n8.x4.trans.shared.b16 {%0,%1,%2,%3}, [%4];"
        : "=r"(r[0]),"=r"(r[1]),"=r"(r[2]),"=r"(r[3]) : "r"(a));
}
__device__ __forceinline__ void mma_hf(float* d, const u32* a, u32 b0, u32 b1){
    asm volatile("mma.sync.aligned.m16n8k16.row.col.f32.f16.f16.f32 "
        "{%0,%1,%2,%3}, {%4,%5,%6,%7}, {%8,%9}, {%0,%1,%2,%3};"
        : "+f"(d[0]),"+f"(d[1]),"+f"(d[2]),"+f"(d[3])
        : "r"(a[0]),"r"(a[1]),"r"(a[2]),"r"(a[3]),"r"(b0),"r"(b1));
}
__device__ __forceinline__ u32 sph(float x, float y){
    __half2 hb = __floats2half2_rn(x, y); return *(u32*)&hb;
}
__device__ __forceinline__ void sp2h(float x, float y, u32& h, u32& l){
    __half2 hb = __floats2half2_rn(x, y);
    float2 hf = __half22float2(hb);
    __half2 lb = __floats2half2_rn(x - hf.x, y - hf.y);
    h = *(u32*)&hb; l = *(u32*)&lb;
}

__global__ void k_init(const float* nlw, const float* ew1, const float* ew2,
                       const float* nw1, const float* nw2){
    const float* srcs[5] = {nlw, ew1, ew2, nw1, nw2};
    const float* src = srcs[blockIdx.x];
    int n = threadIdx.x;
    for (int k = 0; k < 128; ++k)
        *(__half*)(g_Wimg[blockIdx.x] + k*256 + n*2) = __float2half_rn(src[k*128 + n]);
}

// M=32 x N=128 GEMM from fp32 smem rows, 2-term fp16 A (warps 0-7)
__device__ __forceinline__ void gemm_sm(const float* abuf, u32 bimg,
                                        int mb, int cg, int lane, u32 loff, float acc[4][4]){
    const int q = lane>>2, cp = lane&3;
    const int r0 = mb*16 + q, r1 = r0 + 8;
    const bool ok1 = (r1 < 24);
    #pragma unroll
    for (int ks=0; ks<8; ++ks){
        int kc = 16*ks + 2*cp;
        float2 v0 = *(const float2*)&abuf[r0*132+kc];
        float2 v1 = ok1 ? *(const float2*)&abuf[r1*132+kc] : make_float2(0.f,0.f);
        float2 v2 = *(const float2*)&abuf[r0*132+kc+8];
        float2 v3 = ok1 ? *(const float2*)&abuf[r1*132+kc+8] : make_float2(0.f,0.f);
        u32 ah[4], al[4];
        sp2h(v0.x,v0.y,ah[0],al[0]); sp2h(v1.x,v1.y,ah[1],al[1]);
        sp2h(v2.x,v2.y,ah[2],al[2]); sp2h(v3.x,v3.y,ah[3],al[3]);
        #pragma unroll
        for (int j=0;j<2;++j){
            u32 bh[4]; u32 ba = loff + ks*(16*PIT) + (cg*2+j)*32;
            ldsm4t(bh, bimg+ba);
            mma_hf(acc[2*j],   ah, bh[0], bh[1]);
            mma_hf(acc[2*j],   al, bh[0], bh[1]);
            mma_hf(acc[2*j+1], ah, bh[2], bh[3]);
            mma_hf(acc[2*j+1], al, bh[2], bh[3]);
        }
    }
}

__global__ void __launch_bounds__(NT,1) k_fused(
    const int* __restrict__ charges, const float* __restrict__ coords,
    const float* __restrict__ emb,
    const float* __restrict__ eb1, const float* __restrict__ eb2,
    const float* __restrict__ nb1, const float* __restrict__ nb2,
    const float* __restrict__ gw1, const float* __restrict__ gb1,
    const float* __restrict__ gw2, const float* __restrict__ gb2,
    float* __restrict__ out)
{
    extern __shared__ __align__(16) char sm[];
    // all 5 weight images resident; buffers after
    float* hs    = (float*)(sm + 5*IMG);   // 24x132
    float* xs    = hs + 24*132;            // 32x132 (rows 24-31 zero)
    float* sagg  = xs + 32*132;            // 24x132
    float* bb    = sagg + 24*132;          // 512
    const int tid = threadIdx.x, m = blockIdx.x;
    const int wid = tid>>5, lane = tid&31, q = lane>>2, cp = lane&3;
    const u32 loff = (lane&15)*PIT + (lane>>4)*16;
    const u32 sW0 = smaddr(sm), sW1 = sW0+IMG, sW2 = sW0+2*IMG, sW3 = sW0+3*IMG, sW4 = sW0+4*IMG;

    // preload ALL 5 weight images once
    for (int i = tid; i < 5*2048; i += NT){
        int img = i >> 11, idx = i & 2047;
        int k = idx>>4, ch = idx&15;
        cpa16(sW0 + img*IMG + k*PIT + ch*16, g_Wimg[img] + idx*16);
    }
    CP_COMMIT;
    for (int i = tid; i < Aat*128; i += NT)
        hs[(i>>7)*132 + (i&127)] = emb[charges[m*Aat + (i>>7)]*128 + (i&127)];
    for (int i = tid; i < 8*132; i += NT) xs[24*132 + i] = 0.f;
    if (tid < 128){ bb[tid]=eb1[tid]; bb[128+tid]=eb2[tid]; bb[256+tid]=nb1[tid]; bb[384+tid]=nb2[tid]; }

    // RBF -> EA fragments (2 d's per warp), hi-only fp16
    {
        const float* cm = coords + (size_t)m*72;
        for (int i2 = 0; i2 < 2; ++i2){
            int d = wid + 12*i2;
            float ddx=cm[d*3], ddy=cm[d*3+1], ddz=cm[d*3+2];
            float dv[3];
            #pragma unroll
            for (int i=0;i<3;++i){
                int s = q + i*8;
                float ax=cm[s*3]-ddx, ay=cm[s*3+1]-ddy, az=cm[s*3+2]-ddz;
                dv[i] = sqrtf(ax*ax+ay*ay+az*az);
            }
            const float delta = 10.f/127.f, coeff = -0.5f/(delta*delta);
            u32* base = g_EAf + ((size_t)(m*24+d))*2048;
            #pragma unroll
            for (int ks=0; ks<8; ++ks){
                float c0 = (float)(16*ks + 2*cp);
                float v[3][4];
                #pragma unroll
                for (int i=0;i<3;++i)
                    #pragma unroll
                    for (int j=0;j<4;++j){
                        float od = dv[i] - delta*(c0 + (float)((j>>1)*8 + (j&1)));
                        v[i][j] = (fabsf(od) < 1.2f) ? __expf(coeff*od*od) : 0.f;
                    }
                u32* c = base + ks*256;
                *(uint4*)(c + lane*4) = make_uint4(
                    sph(v[0][0],v[0][1]), sph(v[1][0],v[1][1]),
                    sph(v[0][2],v[0][3]), sph(v[1][2],v[1][3]));
                *(uint4*)(c + 128 + lane*4) = make_uint4(
                    sph(v[2][0],v[2][1]), 0u,
                    sph(v[2][2],v[2][3]), 0u);
            }
        }
    }
    CP_WAIT0; __syncthreads();

    const float* b1s = bb;
    const float* b2s = bb + 128;

    for (int layer = 0; layer < 4; ++layer){
        // ===== x = h @ nlw =====
        if (wid < 8){
            const int mb = wid & 1, cg = wid >> 1;
            float acc[4][4];
            #pragma unroll
            for (int i=0;i<4;++i){acc[i][0]=0;acc[i][1]=0;acc[i][2]=0;acc[i][3]=0;}
            gemm_sm(hs, sW0, mb, cg, lane, loff, acc);
            int r0 = mb*16+q, r1 = r0+8;
            #pragma unroll
            for (int jb=0;jb<4;++jb){
                int c = (cg*2+(jb>>1))*16 + (jb&1)*8 + 2*cp;
                *(float2*)&xs[r0*132+c] = make_float2(acc[jb][0], acc[jb][1]);
                if (r1 < 24) *(float2*)&xs[r1*132+c] = make_float2(acc[jb][2], acc[jb][3]);
            }
        }
        __syncthreads();
        // ===== edge phase: 24 d's, 12 warps x 2 passes, M=32, pipelined ldsm =====
        for (int pass=0; pass<2; ++pass){
            const int d = pass*12 + wid;
            u32* base = g_EAf + ((size_t)(m*24+d))*2048;

            u32 a2h[2][8][4];
            #pragma unroll
            for (int half=0; half<2; ++half){
                float acc1[2][8][4];
                #pragma unroll
                for (int i=0;i<8;++i){
                    acc1[0][i][0]=0;acc1[0][i][1]=0;acc1[0][i][2]=0;acc1[0][i][3]=0;
                    acc1[1][i][0]=0;acc1[1][i][1]=0;acc1[1][i][2]=0;acc1[1][i][3]=0;
                }
                uint4 A0 = *(const uint4*)(base + lane*4);
                uint4 A1 = *(const uint4*)(base + 128 + lane*4);
                u32 bfr[2][4];
                ldsm4t(bfr[0], sW1 + loff + (half*4)*32);
                #pragma unroll
                for (int t=0;t<32;++t){
                    const int ks = t>>2, j = t&3;
                    uint4 nA0, nA1;
                    if (j==3 && ks<7){
                        nA0 = *(const uint4*)(base + (ks+1)*256 + lane*4);
                        nA1 = *(const uint4*)(base + (ks+1)*256 + 128 + lane*4);
                    }
                    if (t<31){
                        const int t2=t+1;
                        ldsm4t(bfr[(t+1)&1], sW1 + loff + (t2>>2)*(16*PIT) + (half*4+(t2&3))*32);
                    }
                    u32 ah0[4]={A0.x,A0.y,A0.z,A0.w}, ah1[4]={A1.x,A1.y,A1.z,A1.w};
                    const u32* bh = bfr[t&1];
                    mma_hf(acc1[0][2*j],   ah0,bh[0],bh[1]);
                    mma_hf(acc1[0][2*j+1], ah0,bh[2],bh[3]);
                    mma_hf(acc1[1][2*j],   ah1,bh[0],bh[1]);
                    mma_hf(acc1[1][2*j+1], ah1,bh[2],bh[3]);
                    if (j==3 && ks<7){ A0=nA0; A1=nA1; }
                }
                #pragma unroll
                for (int mb=0;mb<2;++mb)
                    #pragma unroll
                    for (int j=0;j<4;++j){
                        int jj = half*4 + j;
                        int c0 = 16*jj + 2*cp;
                        float bA0=b1s[c0], bA1=b1s[c0+1], bB0=b1s[c0+8], bB1=b1s[c0+9];
                        a2h[mb][jj][0] = sph(ssp(acc1[mb][2*j][0]+bA0),   ssp(acc1[mb][2*j][1]+bA1));
                        a2h[mb][jj][1] = sph(ssp(acc1[mb][2*j][2]+bA0),   ssp(acc1[mb][2*j][3]+bA1));
                        a2h[mb][jj][2] = sph(ssp(acc1[mb][2*j+1][0]+bB0), ssp(acc1[mb][2*j+1][1]+bB1));
                        a2h[mb][jj][3] = sph(ssp(acc1[mb][2*j+1][2]+bB0), ssp(acc1[mb][2*j+1][3]+bB1));
                    }
            }
            // ---- GEMM2 in two N-halves + fused epilogue, pipelined ldsm ----
            #pragma unroll
            for (int hf=0; hf<2; ++hf){
                float acc2[2][8][4];
                #pragma unroll
                for (int i=0;i<8;++i){
                    acc2[0][i][0]=0;acc2[0][i][1]=0;acc2[0][i][2]=0;acc2[0][i][3]=0;
                    acc2[1][i][0]=0;acc2[1][i][1]=0;acc2[1][i][2]=0;acc2[1][i][3]=0;
                }
                u32 bfr[2][4];
                ldsm4t(bfr[0], sW2 + loff + (hf*4)*32);
                #pragma unroll
                for (int t=0;t<32;++t){
                    const int ks = t>>2, j = t&3;
                    if (t<31){
                        const int t2=t+1;
                        ldsm4t(bfr[(t+1)&1], sW2 + loff + (t2>>2)*(16*PIT) + (hf*4+(t2&3))*32);
                    }
                    const u32* bh = bfr[t&1];
                    mma_hf(acc2[0][2*j],   a2h[0][ks],bh[0],bh[1]);
                    mma_hf(acc2[0][2*j+1], a2h[0][ks],bh[2],bh[3]);
                    mma_hf(acc2[1][2*j],   a2h[1][ks],bh[0],bh[1]);
                    mma_hf(acc2[1][2*j+1], a2h[1][ks],bh[2],bh[3]);
                }
                float wag[4][4];
                #pragma unroll
                for (int j=0;j<4;++j){wag[j][0]=0;wag[j][1]=0;wag[j][2]=0;wag[j][3]=0;}
                #pragma unroll
                for (int mb=0;mb<2;++mb){
                    int s0=mb*16+q, s1=s0+8;
                    bool k0=(s0<24)&&(s0!=d), k1=(s1<24)&&(s1!=d);
                    #pragma unroll
                    for (int j=0;j<4;++j){
                        int cA=hf*64+16*j+2*cp, cB=cA+8;
                        float bA0=b2s[cA],bA1=b2s[cA+1],bB0=b2s[cB],bB1=b2s[cB+1];
                        float v00=(acc2[mb][2*j][0]+bA0)*xs[s0*132+cA];
                        float v01=(acc2[mb][2*j][1]+bA1)*xs[s0*132+cA+1];
                        float v10=(acc2[mb][2*j][2]+bA0)*xs[s1*132+cA];
                        float v11=(acc2[mb][2*j][3]+bA1)*xs[s1*132+cA+1];
                        float w00=(acc2[mb][2*j+1][0]+bB0)*xs[s0*132+cB];
                        float w01=(acc2[mb][2*j+1][1]+bB1)*xs[s0*132+cB+1];
                        float w10=(acc2[mb][2*j+1][2]+bB0)*xs[s1*132+cB];
                        float w11=(acc2[mb][2*j+1][3]+bB1)*xs[s1*132+cB+1];
                        *(uint4*)(base + (hf*4+j)*256 + mb*128 + lane*4) = make_uint4(
                            sph(v00,v01), sph(v10,v11), sph(w00,w01), sph(w10,w11));
                        if(k0){ wag[j][0]+=v00; wag[j][1]+=v01; wag[j][2]+=w00; wag[j][3]+=w01; }
                        if(k1){ wag[j][0]+=v10; wag[j][1]+=v11; wag[j][2]+=w10; wag[j][3]+=w11; }
                    }
                }
                #pragma unroll
                for (int j=0;j<4;++j){
                    #pragma unroll
                    for (int u2=0;u2<4;++u2){
                        float tt=wag[j][u2];
                        tt += __shfl_xor_sync(~0u,tt,4); tt += __shfl_xor_sync(~0u,tt,8); tt += __shfl_xor_sync(~0u,tt,16);
                        wag[j][u2]=tt;
                    }
                    if (lane<4){
                        int cA=hf*64+16*j+2*lane;
                        *(float2*)&sagg[d*132+cA]   = make_float2(wag[j][0],wag[j][1]);
                        *(float2*)&sagg[d*132+cA+8] = make_float2(wag[j][2],wag[j][3]);
                    }
                }
            }
        }
        __syncthreads();
        // ===== node phase =====
        if (wid < 8){
            const int mb = wid & 1, cg = wid >> 1;
            float acc[4][4];
            #pragma unroll
            for (int i=0;i<4;++i){acc[i][0]=0;acc[i][1]=0;acc[i][2]=0;acc[i][3]=0;}
            gemm_sm(sagg, sW3, mb, cg, lane, loff, acc);
            int r0 = mb*16+q, r1 = r0+8;
            #pragma unroll
            for (int jb=0;jb<4;++jb){
                int c = (cg*2+(jb>>1))*16 + (jb&1)*8 + 2*cp;
                float b0v = bb[256+c], b1v = bb[256+c+1];
                *(float2*)&xs[r0*132+c] = make_float2(ssp(acc[jb][0]+b0v), ssp(acc[jb][1]+b1v));
                if (r1 < 24) *(float2*)&xs[r1*132+c] = make_float2(ssp(acc[jb][2]+b0v), ssp(acc[jb][3]+b1v));
            }
        }
        __syncthreads();
        if (wid < 8){
            const int mb = wid & 1, cg = wid >> 1;
            float acc[4][4];
            #pragma unroll
            for (int i=0;i<4;++i){acc[i][0]=0;acc[i][1]=0;acc[i][2]=0;acc[i][3]=0;}
            gemm_sm(xs, sW4, mb, cg, lane, loff, acc);
            int r0 = mb*16+q, r1 = r0+8;
            #pragma unroll
            for (int jb=0;jb<4;++jb){
                int c = (cg*2+(jb>>1))*16 + (jb&1)*8 + 2*cp;
                float b0v = bb[384+c], b1v = bb[384+c+1];
                float2 h0 = *(float2*)&hs[r0*132+c];
                h0.x += acc[jb][0]+b0v; h0.y += acc[jb][1]+b1v;
                *(float2*)&hs[r0*132+c] = h0;
                if (r1 < 24){
                    float2 h1 = *(float2*)&hs[r1*132+c];
                    h1.x += acc[jb][2]+b0v; h1.y += acc[jb][3]+b1v;
                    *(float2*)&hs[r1*132+c] = h1;
                }
            }
        }
        __syncthreads();
    }

    // ===== graph readout (reuse dead W0 image space) =====
    float* w1s = (float*)sm;
    for (int i=tid;i<2048;i+=NT) ((float4*)w1s)[i] = ((const float4*)gw1)[i];
    __syncthreads();
    float local = 0.f;
    for (int pos = tid; pos < Aat*64; pos += NT){
        int s = pos >> 6, c = pos & 63;
        float acc = gb1[c];
        #pragma unroll 16
        for (int k = 0; k < 128; ++k) acc += hs[s*132+k] * w1s[k*64+c];
        local += ssp(acc) * gw2[c];
    }
    float* red = sagg;
    red[tid] = local;
    if (tid < 128) red[NT + tid] = 0.f;
    __syncthreads();
    #pragma unroll
    for (int off = 256; off > 0; off >>= 1){
        if (tid < off) red[tid] += red[tid+off];
        __syncthreads();
    }
    if (tid == 0) out[m] = red[0] + (float)Aat * gb2[0];
}

extern "C" void kernel_launch(void* const* d_in, const int* in_sizes, int n_in,
                              void* d_out, int out_size)
{
    const int*   charges = (const int*)  d_in[0];
    const float* coords  = (const float*)d_in[1];
    const float* emb = (const float*)d_in[4];
    const float* nlw = (const float*)d_in[5];
    const float* ew1 = (const float*)d_in[6];
    const float* eb1 = (const float*)d_in[7];
    const float* ew2 = (const float*)d_in[8];
    const float* eb2 = (const float*)d_in[9];
    const float* nw1 = (const float*)d_in[10];
    const float* nb1 = (const float*)d_in[11];
    const float* nw2 = (const float*)d_in[12];
    const float* nb2 = (const float*)d_in[13];
    const float* gw1 = (const float*)d_in[14];
    const float* gb1 = (const float*)d_in[15];
    const float* gw2 = (const float*)d_in[16];
    const float* gb2 = (const float*)d_in[17];
    float* out = (float*)d_out;

    const int SMF = 5*IMG + (24*132 + 32*132 + 24*132 + 512)*4;  // 218368
    cudaFuncSetAttribute(k_fused, cudaFuncAttributeMaxDynamicSharedMemorySize, SMF);

    k_init <<<5, 128>>>(nlw, ew1, ew2, nw1, nw2);
    k_fused<<<Mmol, NT, SMF>>>(charges, coords, emb, eb1, eb2, nb1, nb2,
                               gw1, gb1, gw2, gb2, out);
}

// round 16
// speedup vs baseline: 2.3604x; 1.0524x over previous
#include <cuda_runtime.h>
#include <cuda_fp16.h>

typedef unsigned int u32; typedef unsigned long long u64;
#define Mmol 2048
#define Aat 24
#define PIT 272
#define IMG 34816
#define NT 384

// EA fragments per (m,d): 8 ks-chunks of 256 u32 [hi mb0 | hi mb1], fp16 pairs
__device__ u32 g_EAf[(size_t)Mmol*24*2048];   // 302 MB
__device__ __align__(16) unsigned char g_Wimg[5][32768];   // fp16 weight images

__device__ __forceinline__ u32 smaddr(const void* p){
    u32 a; asm("{ .reg .u64 t; cvta.to.shared.u64 t, %1; cvt.u32.u64 %0, t; }" : "=r"(a) : "l"(p)); return a;
}
__device__ __forceinline__ float ssp(float x){
    return fmaxf(x, 0.f) + __logf(1.f + __expf(-fabsf(x))) - 0.6931471805599453f;
}
__device__ __forceinline__ void cpa16(u32 dst, const void* src){
    asm volatile("cp.async.cg.shared.global [%0], [%1], 16;" :: "r"(dst), "l"(src) : "memory");
}
#define CP_COMMIT asm volatile("cp.async.commit_group;" ::: "memory")
#define CP_WAIT0  asm volatile("cp.async.wait_group 0;"  ::: "memory")
__device__ __forceinline__ void ldsm4t(u32* r, u32 a){
    asm volatile("ldmatrix.sync.aligned.m8n8.x4.trans.shared.b16 {%0,%1,%2,%3}, [%4];"
        : "=r"(r[0]),"=r"(r[1]),"=r"(r[2]),"=r"(r[3]) : "r"(a));
}
__device__ __forceinline__ void mma_hf(float* d, const u32* a, u32 b0, u32 b1){
    asm volatile("mma.sync.aligned.m16n8k16.row.col.f32.f16.f16.f32 "
        "{%0,%1,%2,%3}, {%4,%5,%6,%7}, {%8,%9}, {%0,%1,%2,%3};"
        : "+f"(d[0]),"+f"(d[1]),"+f"(d[2]),"+f"(d[3])
        : "r"(a[0]),"r"(a[1]),"r"(a[2]),"r"(a[3]),"r"(b0),"r"(b1));
}
__device__ __forceinline__ u32 sph(float x, float y){
    __half2 hb = __floats2half2_rn(x, y); return *(u32*)&hb;
}
__device__ __forceinline__ void sp2h(float x, float y, u32& h, u32& l){
    __half2 hb = __floats2half2_rn(x, y);
    float2 hf = __half22float2(hb);
    __half2 lb = __floats2half2_rn(x - hf.x, y - hf.y);
    h = *(u32*)&hb; l = *(u32*)&lb;
}

__global__ void k_init(const float* nlw, const float* ew1, const float* ew2,
                       const float* nw1, const float* nw2){
    const float* srcs[5] = {nlw, ew1, ew2, nw1, nw2};
    const float* src = srcs[blockIdx.x];
    int n = threadIdx.x;
    for (int k = 0; k < 128; ++k)
        *(__half*)(g_Wimg[blockIdx.x] + k*256 + n*2) = __float2half_rn(src[k*128 + n]);
}

// M=32 x N=128 GEMM from fp32 smem rows, 2-term fp16 A (warps 0-7)
__device__ __forceinline__ void gemm_sm(const float* abuf, u32 bimg,
                                        int mb, int cg, int lane, u32 loff, float acc[4][4]){
    const int q = lane>>2, cp = lane&3;
    const int r0 = mb*16 + q, r1 = r0 + 8;
    const bool ok1 = (r1 < 24);
    #pragma unroll
    for (int ks=0; ks<8; ++ks){
        int kc = 16*ks + 2*cp;
        float2 v0 = *(const float2*)&abuf[r0*132+kc];
        float2 v1 = ok1 ? *(const float2*)&abuf[r1*132+kc] : make_float2(0.f,0.f);
        float2 v2 = *(const float2*)&abuf[r0*132+kc+8];
        float2 v3 = ok1 ? *(const float2*)&abuf[r1*132+kc+8] : make_float2(0.f,0.f);
        u32 ah[4], al[4];
        sp2h(v0.x,v0.y,ah[0],al[0]); sp2h(v1.x,v1.y,ah[1],al[1]);
        sp2h(v2.x,v2.y,ah[2],al[2]); sp2h(v3.x,v3.y,ah[3],al[3]);
        #pragma unroll
        for (int j=0;j<2;++j){
            u32 bh[4]; u32 ba = loff + ks*(16*PIT) + (cg*2+j)*32;
            ldsm4t(bh, bimg+ba);
            mma_hf(acc[2*j],   ah, bh[0], bh[1]);
            mma_hf(acc[2*j],   al, bh[0], bh[1]);
            mma_hf(acc[2*j+1], ah, bh[2], bh[3]);
            mma_hf(acc[2*j+1], al, bh[2], bh[3]);
        }
    }
}

__global__ void __launch_bounds__(NT,1) k_fused(
    const int* __restrict__ charges, const float* __restrict__ coords,
    const float* __restrict__ emb,
    const float* __restrict__ eb1, const float* __restrict__ eb2,
    const float* __restrict__ nb1, const float* __restrict__ nb2,
    const float* __restrict__ gw1, const float* __restrict__ gb1,
    const float* __restrict__ gw2, const float* __restrict__ gb2,
    float* __restrict__ out)
{
    extern __shared__ __align__(16) char sm[];
    float* hs    = (float*)(sm + 5*IMG);   // 24x132
    float* xs    = hs + 24*132;            // 32x132 (rows 24-31 zero)
    float* sagg  = xs + 32*132;            // 24x132
    float* bb    = sagg + 24*132;          // 512
    const int tid = threadIdx.x, m = blockIdx.x;
    const int wid = tid>>5, lane = tid&31, q = lane>>2, cp = lane&3;
    const u32 loff = (lane&15)*PIT + (lane>>4)*16;
    const u32 sW0 = smaddr(sm), sW1 = sW0+IMG, sW2 = sW0+2*IMG, sW3 = sW0+3*IMG, sW4 = sW0+4*IMG;

    for (int i = tid; i < 5*2048; i += NT){
        int img = i >> 11, idx = i & 2047;
        int k = idx>>4, ch = idx&15;
        cpa16(sW0 + img*IMG + k*PIT + ch*16, g_Wimg[img] + idx*16);
    }
    CP_COMMIT;
    for (int i = tid; i < Aat*128; i += NT)
        hs[(i>>7)*132 + (i&127)] = emb[charges[m*Aat + (i>>7)]*128 + (i&127)];
    for (int i = tid; i < 8*132; i += NT) xs[24*132 + i] = 0.f;
    if (tid < 128){ bb[tid]=eb1[tid]; bb[128+tid]=eb2[tid]; bb[256+tid]=nb1[tid]; bb[384+tid]=nb2[tid]; }

    // RBF -> EA fragments (2 d's per warp), hi-only fp16
    {
        const float* cm = coords + (size_t)m*72;
        for (int i2 = 0; i2 < 2; ++i2){
            int d = wid + 12*i2;
            float ddx=cm[d*3], ddy=cm[d*3+1], ddz=cm[d*3+2];
            float dv[3];
            #pragma unroll
            for (int i=0;i<3;++i){
                int s = q + i*8;
                float ax=cm[s*3]-ddx, ay=cm[s*3+1]-ddy, az=cm[s*3+2]-ddz;
                dv[i] = sqrtf(ax*ax+ay*ay+az*az);
            }
            const float delta = 10.f/127.f, coeff = -0.5f/(delta*delta);
            u32* base = g_EAf + ((size_t)(m*24+d))*2048;
            #pragma unroll
            for (int ks=0; ks<8; ++ks){
                float c0 = (float)(16*ks + 2*cp);
                float v[3][4];
                #pragma unroll
                for (int i=0;i<3;++i)
                    #pragma unroll
                    for (int j=0;j<4;++j){
                        float od = dv[i] - delta*(c0 + (float)((j>>1)*8 + (j&1)));
                        v[i][j] = (fabsf(od) < 1.2f) ? __expf(coeff*od*od) : 0.f;
                    }
                u32* c = base + ks*256;
                *(uint4*)(c + lane*4) = make_uint4(
                    sph(v[0][0],v[0][1]), sph(v[1][0],v[1][1]),
                    sph(v[0][2],v[0][3]), sph(v[1][2],v[1][3]));
                *(uint4*)(c + 128 + lane*4) = make_uint4(
                    sph(v[2][0],v[2][1]), 0u,
                    sph(v[2][2],v[2][3]), 0u);
            }
        }
    }
    CP_WAIT0; __syncthreads();

    const float* b1s = bb;
    const float* b2s = bb + 128;

    for (int layer = 0; layer < 4; ++layer){
        const bool storeEA = (layer != 3);
        // ===== x = h @ nlw =====
        if (wid < 8){
            const int mb = wid & 1, cg = wid >> 1;
            float acc[4][4];
            #pragma unroll
            for (int i=0;i<4;++i){acc[i][0]=0;acc[i][1]=0;acc[i][2]=0;acc[i][3]=0;}
            gemm_sm(hs, sW0, mb, cg, lane, loff, acc);
            int r0 = mb*16+q, r1 = r0+8;
            #pragma unroll
            for (int jb=0;jb<4;++jb){
                int c = (cg*2+(jb>>1))*16 + (jb&1)*8 + 2*cp;
                *(float2*)&xs[r0*132+c] = make_float2(acc[jb][0], acc[jb][1]);
                if (r1 < 24) *(float2*)&xs[r1*132+c] = make_float2(acc[jb][2], acc[jb][3]);
            }
        }
        __syncthreads();
        // ===== edge phase: 24 d's, 12 warps x 2 passes, M=32 =====
        for (int pass=0; pass<2; ++pass){
            const int d = pass*12 + wid;
            u32* base = g_EAf + ((size_t)(m*24+d))*2048;

            u32 a2h[2][8][4];
            #pragma unroll
            for (int half=0; half<2; ++half){
                float acc1[2][8][4];
                #pragma unroll
                for (int i=0;i<8;++i){
                    acc1[0][i][0]=0;acc1[0][i][1]=0;acc1[0][i][2]=0;acc1[0][i][3]=0;
                    acc1[1][i][0]=0;acc1[1][i][1]=0;acc1[1][i][2]=0;acc1[1][i][3]=0;
                }
                uint4 A0 = *(const uint4*)(base + lane*4);
                uint4 A1 = *(const uint4*)(base + 128 + lane*4);
                u32 bfr[2][4];
                ldsm4t(bfr[0], sW1 + loff + (half*4)*32);
                #pragma unroll
                for (int t=0;t<32;++t){
                    const int ks = t>>2, j = t&3;
                    uint4 nA0, nA1;
                    if (j==3 && ks<7){
                        nA0 = *(const uint4*)(base + (ks+1)*256 + lane*4);
                        nA1 = *(const uint4*)(base + (ks+1)*256 + 128 + lane*4);
                    }
                    if (t<31){
                        const int t2=t+1;
                        ldsm4t(bfr[(t+1)&1], sW1 + loff + (t2>>2)*(16*PIT) + (half*4+(t2&3))*32);
                    }
                    u32 ah0[4]={A0.x,A0.y,A0.z,A0.w}, ah1[4]={A1.x,A1.y,A1.z,A1.w};
                    const u32* bh = bfr[t&1];
                    mma_hf(acc1[0][2*j],   ah0,bh[0],bh[1]);
                    mma_hf(acc1[0][2*j+1], ah0,bh[2],bh[3]);
                    mma_hf(acc1[1][2*j],   ah1,bh[0],bh[1]);
                    mma_hf(acc1[1][2*j+1], ah1,bh[2],bh[3]);
                    if (j==3 && ks<7){ A0=nA0; A1=nA1; }
                }
                #pragma unroll
                for (int mb=0;mb<2;++mb)
                    #pragma unroll
                    for (int j=0;j<4;++j){
                        int jj = half*4 + j;
                        int c0 = 16*jj + 2*cp;
                        float bA0=b1s[c0], bA1=b1s[c0+1], bB0=b1s[c0+8], bB1=b1s[c0+9];
                        a2h[mb][jj][0] = sph(ssp(acc1[mb][2*j][0]+bA0),   ssp(acc1[mb][2*j][1]+bA1));
                        a2h[mb][jj][1] = sph(ssp(acc1[mb][2*j][2]+bA0),   ssp(acc1[mb][2*j][3]+bA1));
                        a2h[mb][jj][2] = sph(ssp(acc1[mb][2*j+1][0]+bB0), ssp(acc1[mb][2*j+1][1]+bB1));
                        a2h[mb][jj][3] = sph(ssp(acc1[mb][2*j+1][2]+bB0), ssp(acc1[mb][2*j+1][3]+bB1));
                    }
            }
            // ---- GEMM2 in two N-halves + fused epilogue, depth-2 ldsm ----
            #pragma unroll
            for (int hf=0; hf<2; ++hf){
                float acc2[2][8][4];
                #pragma unroll
                for (int i=0;i<8;++i){
                    acc2[0][i][0]=0;acc2[0][i][1]=0;acc2[0][i][2]=0;acc2[0][i][3]=0;
                    acc2[1][i][0]=0;acc2[1][i][1]=0;acc2[1][i][2]=0;acc2[1][i][3]=0;
                }
                u32 bfr[3][4];
                ldsm4t(bfr[0], sW2 + loff + (hf*4)*32);
                ldsm4t(bfr[1], sW2 + loff + (hf*4+1)*32);
                #pragma unroll
                for (int t=0;t<32;++t){
                    const int ks = t>>2, j = t&3;
                    if (t<30){
                        const int t2=t+2;
                        ldsm4t(bfr[(t+2)%3], sW2 + loff + (t2>>2)*(16*PIT) + (hf*4+(t2&3))*32);
                    }
                    const u32* bh = bfr[t%3];
                    mma_hf(acc2[0][2*j],   a2h[0][ks],bh[0],bh[1]);
                    mma_hf(acc2[0][2*j+1], a2h[0][ks],bh[2],bh[3]);
                    mma_hf(acc2[1][2*j],   a2h[1][ks],bh[0],bh[1]);
                    mma_hf(acc2[1][2*j+1], a2h[1][ks],bh[2],bh[3]);
                }
                float wag[4][4];
                #pragma unroll
                for (int j=0;j<4;++j){wag[j][0]=0;wag[j][1]=0;wag[j][2]=0;wag[j][3]=0;}
                #pragma unroll
                for (int mb=0;mb<2;++mb){
                    int s0=mb*16+q, s1=s0+8;
                    bool k0=(s0<24)&&(s0!=d), k1=(s1<24)&&(s1!=d);
                    #pragma unroll
                    for (int j=0;j<4;++j){
                        int cA=hf*64+16*j+2*cp, cB=cA+8;
                        float bA0=b2s[cA],bA1=b2s[cA+1],bB0=b2s[cB],bB1=b2s[cB+1];
                        float v00=(acc2[mb][2*j][0]+bA0)*xs[s0*132+cA];
                        float v01=(acc2[mb][2*j][1]+bA1)*xs[s0*132+cA+1];
                        float v10=(acc2[mb][2*j][2]+bA0)*xs[s1*132+cA];
                        float v11=(acc2[mb][2*j][3]+bA1)*xs[s1*132+cA+1];
                        float w00=(acc2[mb][2*j+1][0]+bB0)*xs[s0*132+cB];
                        float w01=(acc2[mb][2*j+1][1]+bB1)*xs[s0*132+cB+1];
                        float w10=(acc2[mb][2*j+1][2]+bB0)*xs[s1*132+cB];
                        float w11=(acc2[mb][2*j+1][3]+bB1)*xs[s1*132+cB+1];
                        if (storeEA)
                            *(uint4*)(base + (hf*4+j)*256 + mb*128 + lane*4) = make_uint4(
                                sph(v00,v01), sph(v10,v11), sph(w00,w01), sph(w10,w11));
                        if(k0){ wag[j][0]+=v00; wag[j][1]+=v01; wag[j][2]+=w00; wag[j][3]+=w01; }
                        if(k1){ wag[j][0]+=v10; wag[j][1]+=v11; wag[j][2]+=w10; wag[j][3]+=w11; }
                    }
                }
                #pragma unroll
                for (int j=0;j<4;++j){
                    #pragma unroll
                    for (int u2=0;u2<4;++u2){
                        float tt=wag[j][u2];
                        tt += __shfl_xor_sync(~0u,tt,4); tt += __shfl_xor_sync(~0u,tt,8); tt += __shfl_xor_sync(~0u,tt,16);
                        wag[j][u2]=tt;
                    }
                    if (lane<4){
                        int cA=hf*64+16*j+2*lane;
                        *(float2*)&sagg[d*132+cA]   = make_float2(wag[j][0],wag[j][1]);
                        *(float2*)&sagg[d*132+cA+8] = make_float2(wag[j][2],wag[j][3]);
                    }
                }
            }
        }
        __syncthreads();
        // ===== node phase =====
        if (wid < 8){
            const int mb = wid & 1, cg = wid >> 1;
            float acc[4][4];
            #pragma unroll
            for (int i=0;i<4;++i){acc[i][0]=0;acc[i][1]=0;acc[i][2]=0;acc[i][3]=0;}
            gemm_sm(sagg, sW3, mb, cg, lane, loff, acc);
            int r0 = mb*16+q, r1 = r0+8;
            #pragma unroll
            for (int jb=0;jb<4;++jb){
                int c = (cg*2+(jb>>1))*16 + (jb&1)*8 + 2*cp;
                float b0v = bb[256+c], b1v = bb[256+c+1];
                *(float2*)&xs[r0*132+c] = make_float2(ssp(acc[jb][0]+b0v), ssp(acc[jb][1]+b1v));
                if (r1 < 24) *(float2*)&xs[r1*132+c] = make_float2(ssp(acc[jb][2]+b0v), ssp(acc[jb][3]+b1v));
            }
        }
        __syncthreads();
        if (wid < 8){
            const int mb = wid & 1, cg = wid >> 1;
            float acc[4][4];
            #pragma unroll
            for (int i=0;i<4;++i){acc[i][0]=0;acc[i][1]=0;acc[i][2]=0;acc[i][3]=0;}
            gemm_sm(xs, sW4, mb, cg, lane, loff, acc);
            int r0 = mb*16+q, r1 = r0+8;
            #pragma unroll
            for (int jb=0;jb<4;++jb){
                int c = (cg*2+(jb>>1))*16 + (jb&1)*8 + 2*cp;
                float b0v = bb[384+c], b1v = bb[384+c+1];
                float2 h0 = *(float2*)&hs[r0*132+c];
                h0.x += acc[jb][0]+b0v; h0.y += acc[jb][1]+b1v;
                *(float2*)&hs[r0*132+c] = h0;
                if (r1 < 24){
                    float2 h1 = *(float2*)&hs[r1*132+c];
                    h1.x += acc[jb][2]+b0v; h1.y += acc[jb][3]+b1v;
                    *(float2*)&hs[r1*132+c] = h1;
                }
            }
        }
        __syncthreads();
    }

    // ===== graph readout (reuse dead W0 image space) =====
    float* w1s = (float*)sm;
    for (int i=tid;i<2048;i+=NT) ((float4*)w1s)[i] = ((const float4*)gw1)[i];
    __syncthreads();
    float local = 0.f;
    for (int pos = tid; pos < Aat*64; pos += NT){
        int s = pos >> 6, c = pos & 63;
        float acc = gb1[c];
        #pragma unroll 16
        for (int k = 0; k < 128; ++k) acc += hs[s*132+k] * w1s[k*64+c];
        local += ssp(acc) * gw2[c];
    }
    float* red = sagg;
    red[tid] = local;
    if (tid < 128) red[NT + tid] = 0.f;
    __syncthreads();
    #pragma unroll
    for (int off = 256; off > 0; off >>= 1){
        if (tid < off) red[tid] += red[tid+off];
        __syncthreads();
    }
    if (tid == 0) out[m] = red[0] + (float)Aat * gb2[0];
}

extern "C" void kernel_launch(void* const* d_in, const int* in_sizes, int n_in,
                              void* d_out, int out_size)
{
    const int*   charges = (const int*)  d_in[0];
    const float* coords  = (const float*)d_in[1];
    const float* emb = (const float*)d_in[4];
    const float* nlw = (const float*)d_in[5];
    const float* ew1 = (const float*)d_in[6];
    const float* eb1 = (const float*)d_in[7];
    const float* ew2 = (const float*)d_in[8];
    const float* eb2 = (const float*)d_in[9];
    const float* nw1 = (const float*)d_in[10];
    const float* nb1 = (const float*)d_in[11];
    const float* nw2 = (const float*)d_in[12];
    const float* nb2 = (const float*)d_in[13];
    const float* gw1 = (const float*)d_in[14];
    const float* gb1 = (const float*)d_in[15];
    const float* gw2 = (const float*)d_in[16];
    const float* gb2 = (const float*)d_in[17];
    float* out = (float*)d_out;

    const int SMF = 5*IMG + (24*132 + 32*132 + 24*132 + 512)*4;  // 218368
    cudaFuncSetAttribute(k_fused, cudaFuncAttributeMaxDynamicSharedMemorySize, SMF);

    k_init <<<5, 128>>>(nlw, ew1, ew2, nw1, nw2);
    k_fused<<<Mmol, NT, SMF>>>(charges, coords, emb, eb1, eb2, nb1, nb2,
                               gw1, gb1, gw2, gb2, out);
}

// round 17
// speedup vs baseline: 2.4258x; 1.0277x over previous
#include <cuda_runtime.h>
#include <cuda_fp16.h>

typedef unsigned int u32; typedef unsigned long long u64;
#define Mmol 2048
#define Aat 24
#define PIT 272
#define IMG 34816
#define NT 384

// EA fragments per (m,d): 8 ks-chunks of 256 u32 [hi mb0 | hi mb1], fp16 pairs
__device__ u32 g_EAf[(size_t)Mmol*24*2048];   // 302 MB
__device__ __align__(16) unsigned char g_Wimg[5][32768];   // fp16 weight images

__device__ __forceinline__ u32 smaddr(const void* p){
    u32 a; asm("{ .reg .u64 t; cvta.to.shared.u64 t, %1; cvt.u32.u64 %0, t; }" : "=r"(a) : "l"(p)); return a;
}
__device__ __forceinline__ float ssp(float x){
    return fmaxf(x, 0.f) + __logf(1.f + __expf(-fabsf(x))) - 0.6931471805599453f;
}
__device__ __forceinline__ void cpa16(u32 dst, const void* src){
    asm volatile("cp.async.cg.shared.global [%0], [%1], 16;" :: "r"(dst), "l"(src) : "memory");
}
#define CP_COMMIT asm volatile("cp.async.commit_group;" ::: "memory")
#define CP_WAIT0  asm volatile("cp.async.wait_group 0;"  ::: "memory")
__device__ __forceinline__ void ldsm4t(u32* r, u32 a){
    asm volatile("ldmatrix.sync.aligned.m8n8.x4.trans.shared.b16 {%0,%1,%2,%3}, [%4];"
        : "=r"(r[0]),"=r"(r[1]),"=r"(r[2]),"=r"(r[3]) : "r"(a));
}
__device__ __forceinline__ void mma_hf(float* d, const u32* a, u32 b0, u32 b1){
    asm volatile("mma.sync.aligned.m16n8k16.row.col.f32.f16.f16.f32 "
        "{%0,%1,%2,%3}, {%4,%5,%6,%7}, {%8,%9}, {%0,%1,%2,%3};"
        : "+f"(d[0]),"+f"(d[1]),"+f"(d[2]),"+f"(d[3])
        : "r"(a[0]),"r"(a[1]),"r"(a[2]),"r"(a[3]),"r"(b0),"r"(b1));
}
__device__ __forceinline__ u32 sph(float x, float y){
    __half2 hb = __floats2half2_rn(x, y); return *(u32*)&hb;
}
__device__ __forceinline__ void sp2h(float x, float y, u32& h, u32& l){
    __half2 hb = __floats2half2_rn(x, y);
    float2 hf = __half22float2(hb);
    __half2 lb = __floats2half2_rn(x - hf.x, y - hf.y);
    h = *(u32*)&hb; l = *(u32*)&lb;
}

__global__ void k_init(const float* nlw, const float* ew1, const float* ew2,
                       const float* nw1, const float* nw2){
    const float* srcs[5] = {nlw, ew1, ew2, nw1, nw2};
    const float* src = srcs[blockIdx.x];
    int n = threadIdx.x;
    for (int k = 0; k < 128; ++k)
        *(__half*)(g_Wimg[blockIdx.x] + k*256 + n*2) = __float2half_rn(src[k*128 + n]);
}

// M=32 x N=128 GEMM from fp32 smem rows, 2-term fp16 A (warps 0-7)
__device__ __forceinline__ void gemm_sm(const float* abuf, u32 bimg,
                                        int mb, int cg, int lane, u32 loff, float acc[4][4]){
    const int q = lane>>2, cp = lane&3;
    const int r0 = mb*16 + q, r1 = r0 + 8;
    const bool ok1 = (r1 < 24);
    #pragma unroll
    for (int ks=0; ks<8; ++ks){
        int kc = 16*ks + 2*cp;
        float2 v0 = *(const float2*)&abuf[r0*132+kc];
        float2 v1 = ok1 ? *(const float2*)&abuf[r1*132+kc] : make_float2(0.f,0.f);
        float2 v2 = *(const float2*)&abuf[r0*132+kc+8];
        float2 v3 = ok1 ? *(const float2*)&abuf[r1*132+kc+8] : make_float2(0.f,0.f);
        u32 ah[4], al[4];
        sp2h(v0.x,v0.y,ah[0],al[0]); sp2h(v1.x,v1.y,ah[1],al[1]);
        sp2h(v2.x,v2.y,ah[2],al[2]); sp2h(v3.x,v3.y,ah[3],al[3]);
        #pragma unroll
        for (int j=0;j<2;++j){
            u32 bh[4]; u32 ba = loff + ks*(16*PIT) + (cg*2+j)*32;
            ldsm4t(bh, bimg+ba);
            mma_hf(acc[2*j],   ah, bh[0], bh[1]);
            mma_hf(acc[2*j],   al, bh[0], bh[1]);
            mma_hf(acc[2*j+1], ah, bh[2], bh[3]);
            mma_hf(acc[2*j+1], al, bh[2], bh[3]);
        }
    }
}

__global__ void __launch_bounds__(NT,1) k_fused(
    const int* __restrict__ charges, const float* __restrict__ coords,
    const float* __restrict__ emb,
    const float* __restrict__ eb1, const float* __restrict__ eb2,
    const float* __restrict__ nb1, const float* __restrict__ nb2,
    const float* __restrict__ gw1, const float* __restrict__ gb1,
    const float* __restrict__ gw2, const float* __restrict__ gb2,
    float* __restrict__ out)
{
    extern __shared__ __align__(16) char sm[];
    float* hs    = (float*)(sm + 5*IMG);   // 24x132
    float* xs    = hs + 24*132;            // 32x132 (rows 24-31 zero)
    float* sagg  = xs + 32*132;            // 24x132
    float* bb    = sagg + 24*132;          // 512
    const int tid = threadIdx.x, m = blockIdx.x;
    const int wid = tid>>5, lane = tid&31, q = lane>>2, cp = lane&3;
    const u32 loff = (lane&15)*PIT + (lane>>4)*16;
    const u32 sW0 = smaddr(sm), sW1 = sW0+IMG, sW2 = sW0+2*IMG, sW3 = sW0+3*IMG, sW4 = sW0+4*IMG;

    for (int i = tid; i < 5*2048; i += NT){
        int img = i >> 11, idx = i & 2047;
        int k = idx>>4, ch = idx&15;
        cpa16(sW0 + img*IMG + k*PIT + ch*16, g_Wimg[img] + idx*16);
    }
    CP_COMMIT;
    for (int i = tid; i < Aat*128; i += NT)
        hs[(i>>7)*132 + (i&127)] = emb[charges[m*Aat + (i>>7)]*128 + (i&127)];
    for (int i = tid; i < 8*132; i += NT) xs[24*132 + i] = 0.f;
    if (tid < 128){ bb[tid]=eb1[tid]; bb[128+tid]=eb2[tid]; bb[256+tid]=nb1[tid]; bb[384+tid]=nb2[tid]; }

    // RBF -> EA fragments (2 d's per warp), hi-only fp16
    {
        const float* cm = coords + (size_t)m*72;
        for (int i2 = 0; i2 < 2; ++i2){
            int d = wid + 12*i2;
            float ddx=cm[d*3], ddy=cm[d*3+1], ddz=cm[d*3+2];
            float dv[3];
            #pragma unroll
            for (int i=0;i<3;++i){
                int s = q + i*8;
                float ax=cm[s*3]-ddx, ay=cm[s*3+1]-ddy, az=cm[s*3+2]-ddz;
                dv[i] = sqrtf(ax*ax+ay*ay+az*az);
            }
            const float delta = 10.f/127.f, coeff = -0.5f/(delta*delta);
            u32* base = g_EAf + ((size_t)(m*24+d))*2048;
            #pragma unroll
            for (int ks=0; ks<8; ++ks){
                float c0 = (float)(16*ks + 2*cp);
                float v[3][4];
                #pragma unroll
                for (int i=0;i<3;++i)
                    #pragma unroll
                    for (int j=0;j<4;++j){
                        float od = dv[i] - delta*(c0 + (float)((j>>1)*8 + (j&1)));
                        v[i][j] = (fabsf(od) < 1.2f) ? __expf(coeff*od*od) : 0.f;
                    }
                u32* c = base + ks*256;
                *(uint4*)(c + lane*4) = make_uint4(
                    sph(v[0][0],v[0][1]), sph(v[1][0],v[1][1]),
                    sph(v[0][2],v[0][3]), sph(v[1][2],v[1][3]));
                *(uint4*)(c + 128 + lane*4) = make_uint4(
                    sph(v[2][0],v[2][1]), 0u,
                    sph(v[2][2],v[2][3]), 0u);
            }
        }
    }
    CP_WAIT0; __syncthreads();

    const float* b1s = bb;
    const float* b2s = bb + 128;

    for (int layer = 0; layer < 4; ++layer){
        const bool storeEA = (layer != 3);
        // ===== x = h @ nlw =====
        if (wid < 8){
            const int mb = wid & 1, cg = wid >> 1;
            float acc[4][4];
            #pragma unroll
            for (int i=0;i<4;++i){acc[i][0]=0;acc[i][1]=0;acc[i][2]=0;acc[i][3]=0;}
            gemm_sm(hs, sW0, mb, cg, lane, loff, acc);
            int r0 = mb*16+q, r1 = r0+8;
            #pragma unroll
            for (int jb=0;jb<4;++jb){
                int c = (cg*2+(jb>>1))*16 + (jb&1)*8 + 2*cp;
                *(float2*)&xs[r0*132+c] = make_float2(acc[jb][0], acc[jb][1]);
                if (r1 < 24) *(float2*)&xs[r1*132+c] = make_float2(acc[jb][2], acc[jb][3]);
            }
        }
        __syncthreads();
        // ===== edge phase: 24 d's, 12 warps x 2 passes, M=32 =====
        for (int pass=0; pass<2; ++pass){
            const int d = pass*12 + wid;
            u32* base = g_EAf + ((size_t)(m*24+d))*2048;

            u32 a2h[2][8][4];
            #pragma unroll
            for (int half=0; half<2; ++half){
                float acc1[2][8][4];
                #pragma unroll
                for (int i=0;i<8;++i){
                    acc1[0][i][0]=0;acc1[0][i][1]=0;acc1[0][i][2]=0;acc1[0][i][3]=0;
                    acc1[1][i][0]=0;acc1[1][i][1]=0;acc1[1][i][2]=0;acc1[1][i][3]=0;
                }
                // A-fragment ring of 3 (prefetch 2 ks ahead)
                uint4 Ar0[3], Ar1[3];
                Ar0[0] = *(const uint4*)(base + lane*4);
                Ar1[0] = *(const uint4*)(base + 128 + lane*4);
                Ar0[1] = *(const uint4*)(base + 256 + lane*4);
                Ar1[1] = *(const uint4*)(base + 256 + 128 + lane*4);
                // B ldsm ring of 3
                u32 bfr[3][4];
                ldsm4t(bfr[0], sW1 + loff + (half*4)*32);
                ldsm4t(bfr[1], sW1 + loff + (half*4+1)*32);
                #pragma unroll
                for (int t=0;t<32;++t){
                    const int ks = t>>2, j = t&3;
                    if (j==0 && ks<6){
                        Ar0[(ks+2)%3] = *(const uint4*)(base + (ks+2)*256 + lane*4);
                        Ar1[(ks+2)%3] = *(const uint4*)(base + (ks+2)*256 + 128 + lane*4);
                    }
                    if (t<30){
                        const int t2=t+2;
                        ldsm4t(bfr[(t+2)%3], sW1 + loff + (t2>>2)*(16*PIT) + (half*4+(t2&3))*32);
                    }
                    const uint4 A0 = Ar0[ks%3], A1 = Ar1[ks%3];
                    u32 ah0[4]={A0.x,A0.y,A0.z,A0.w}, ah1[4]={A1.x,A1.y,A1.z,A1.w};
                    const u32* bh = bfr[t%3];
                    mma_hf(acc1[0][2*j],   ah0,bh[0],bh[1]);
                    mma_hf(acc1[0][2*j+1], ah0,bh[2],bh[3]);
                    mma_hf(acc1[1][2*j],   ah1,bh[0],bh[1]);
                    mma_hf(acc1[1][2*j+1], ah1,bh[2],bh[3]);
                }
                #pragma unroll
                for (int mb=0;mb<2;++mb)
                    #pragma unroll
                    for (int j=0;j<4;++j){
                        int jj = half*4 + j;
                        int c0 = 16*jj + 2*cp;
                        float bA0=b1s[c0], bA1=b1s[c0+1], bB0=b1s[c0+8], bB1=b1s[c0+9];
                        a2h[mb][jj][0] = sph(ssp(acc1[mb][2*j][0]+bA0),   ssp(acc1[mb][2*j][1]+bA1));
                        a2h[mb][jj][1] = sph(ssp(acc1[mb][2*j][2]+bA0),   ssp(acc1[mb][2*j][3]+bA1));
                        a2h[mb][jj][2] = sph(ssp(acc1[mb][2*j+1][0]+bB0), ssp(acc1[mb][2*j+1][1]+bB1));
                        a2h[mb][jj][3] = sph(ssp(acc1[mb][2*j+1][2]+bB0), ssp(acc1[mb][2*j+1][3]+bB1));
                    }
            }
            // ---- GEMM2 in two N-halves + fused epilogue, depth-2 ldsm ----
            #pragma unroll
            for (int hf=0; hf<2; ++hf){
                float acc2[2][8][4];
                #pragma unroll
                for (int i=0;i<8;++i){
                    acc2[0][i][0]=0;acc2[0][i][1]=0;acc2[0][i][2]=0;acc2[0][i][3]=0;
                    acc2[1][i][0]=0;acc2[1][i][1]=0;acc2[1][i][2]=0;acc2[1][i][3]=0;
                }
                u32 bfr[3][4];
                ldsm4t(bfr[0], sW2 + loff + (hf*4)*32);
                ldsm4t(bfr[1], sW2 + loff + (hf*4+1)*32);
                #pragma unroll
                for (int t=0;t<32;++t){
                    const int ks = t>>2, j = t&3;
                    if (t<30){
                        const int t2=t+2;
                        ldsm4t(bfr[(t+2)%3], sW2 + loff + (t2>>2)*(16*PIT) + (hf*4+(t2&3))*32);
                    }
                    const u32* bh = bfr[t%3];
                    mma_hf(acc2[0][2*j],   a2h[0][ks],bh[0],bh[1]);
                    mma_hf(acc2[0][2*j+1], a2h[0][ks],bh[2],bh[3]);
                    mma_hf(acc2[1][2*j],   a2h[1][ks],bh[0],bh[1]);
                    mma_hf(acc2[1][2*j+1], a2h[1][ks],bh[2],bh[3]);
                }
                float wag[4][4];
                #pragma unroll
                for (int j=0;j<4;++j){wag[j][0]=0;wag[j][1]=0;wag[j][2]=0;wag[j][3]=0;}
                #pragma unroll
                for (int mb=0;mb<2;++mb){
                    int s0=mb*16+q, s1=s0+8;
                    bool k0=(s0<24)&&(s0!=d), k1=(s1<24)&&(s1!=d);
                    #pragma unroll
                    for (int j=0;j<4;++j){
                        int cA=hf*64+16*j+2*cp, cB=cA+8;
                        float bA0=b2s[cA],bA1=b2s[cA+1],bB0=b2s[cB],bB1=b2s[cB+1];
                        float v00=(acc2[mb][2*j][0]+bA0)*xs[s0*132+cA];
                        float v01=(acc2[mb][2*j][1]+bA1)*xs[s0*132+cA+1];
                        float v10=(acc2[mb][2*j][2]+bA0)*xs[s1*132+cA];
                        float v11=(acc2[mb][2*j][3]+bA1)*xs[s1*132+cA+1];
                        float w00=(acc2[mb][2*j+1][0]+bB0)*xs[s0*132+cB];
                        float w01=(acc2[mb][2*j+1][1]+bB1)*xs[s0*132+cB+1];
                        float w10=(acc2[mb][2*j+1][2]+bB0)*xs[s1*132+cB];
                        float w11=(acc2[mb][2*j+1][3]+bB1)*xs[s1*132+cB+1];
                        if (storeEA)
                            *(uint4*)(base + (hf*4+j)*256 + mb*128 + lane*4) = make_uint4(
                                sph(v00,v01), sph(v10,v11), sph(w00,w01), sph(w10,w11));
                        if(k0){ wag[j][0]+=v00; wag[j][1]+=v01; wag[j][2]+=w00; wag[j][3]+=w01; }
                        if(k1){ wag[j][0]+=v10; wag[j][1]+=v11; wag[j][2]+=w10; wag[j][3]+=w11; }
                    }
                }
                #pragma unroll
                for (int j=0;j<4;++j){
                    #pragma unroll
                    for (int u2=0;u2<4;++u2){
                        float tt=wag[j][u2];
                        tt += __shfl_xor_sync(~0u,tt,4); tt += __shfl_xor_sync(~0u,tt,8); tt += __shfl_xor_sync(~0u,tt,16);
                        wag[j][u2]=tt;
                    }
                    if (lane<4){
                        int cA=hf*64+16*j+2*lane;
                        *(float2*)&sagg[d*132+cA]   = make_float2(wag[j][0],wag[j][1]);
                        *(float2*)&sagg[d*132+cA+8] = make_float2(wag[j][2],wag[j][3]);
                    }
                }
            }
        }
        __syncthreads();
        // ===== node phase =====
        if (wid < 8){
            const int mb = wid & 1, cg = wid >> 1;
            float acc[4][4];
            #pragma unroll
            for (int i=0;i<4;++i){acc[i][0]=0;acc[i][1]=0;acc[i][2]=0;acc[i][3]=0;}
            gemm_sm(sagg, sW3, mb, cg, lane, loff, acc);
            int r0 = mb*16+q, r1 = r0+8;
            #pragma unroll
            for (int jb=0;jb<4;++jb){
                int c = (cg*2+(jb>>1))*16 + (jb&1)*8 + 2*cp;
                float b0v = bb[256+c], b1v = bb[256+c+1];
                *(float2*)&xs[r0*132+c] = make_float2(ssp(acc[jb][0]+b0v), ssp(acc[jb][1]+b1v));
                if (r1 < 24) *(float2*)&xs[r1*132+c] = make_float2(ssp(acc[jb][2]+b0v), ssp(acc[jb][3]+b1v));
            }
        }
        __syncthreads();
        if (wid < 8){
            const int mb = wid & 1, cg = wid >> 1;
            float acc[4][4];
            #pragma unroll
            for (int i=0;i<4;++i){acc[i][0]=0;acc[i][1]=0;acc[i][2]=0;acc[i][3]=0;}
            gemm_sm(xs, sW4, mb, cg, lane, loff, acc);
            int r0 = mb*16+q, r1 = r0+8;
            #pragma unroll
            for (int jb=0;jb<4;++jb){
                int c = (cg*2+(jb>>1))*16 + (jb&1)*8 + 2*cp;
                float b0v = bb[384+c], b1v = bb[384+c+1];
                float2 h0 = *(float2*)&hs[r0*132+c];
                h0.x += acc[jb][0]+b0v; h0.y += acc[jb][1]+b1v;
                *(float2*)&hs[r0*132+c] = h0;
                if (r1 < 24){
                    float2 h1 = *(float2*)&hs[r1*132+c];
                    h1.x += acc[jb][2]+b0v; h1.y += acc[jb][3]+b1v;
                    *(float2*)&hs[r1*132+c] = h1;
                }
            }
        }
        __syncthreads();
    }

    // ===== graph readout (reuse dead W0 image space) =====
    float* w1s = (float*)sm;
    for (int i=tid;i<2048;i+=NT) ((float4*)w1s)[i] = ((const float4*)gw1)[i];
    __syncthreads();
    float local = 0.f;
    for (int pos = tid; pos < Aat*64; pos += NT){
        int s = pos >> 6, c = pos & 63;
        float acc = gb1[c];
        #pragma unroll 16
        for (int k = 0; k < 128; ++k) acc += hs[s*132+k] * w1s[k*64+c];
        local += ssp(acc) * gw2[c];
    }
    float* red = sagg;
    red[tid] = local;
    if (tid < 128) red[NT + tid] = 0.f;
    __syncthreads();
    #pragma unroll
    for (int off = 256; off > 0; off >>= 1){
        if (tid < off) red[tid] += red[tid+off];
        __syncthreads();
    }
    if (tid == 0) out[m] = red[0] + (float)Aat * gb2[0];
}

extern "C" void kernel_launch(void* const* d_in, const int* in_sizes, int n_in,
                              void* d_out, int out_size)
{
    const int*   charges = (const int*)  d_in[0];
    const float* coords  = (const float*)d_in[1];
    const float* emb = (const float*)d_in[4];
    const float* nlw = (const float*)d_in[5];
    const float* ew1 = (const float*)d_in[6];
    const float* eb1 = (const float*)d_in[7];
    const float* ew2 = (const float*)d_in[8];
    const float* eb2 = (const float*)d_in[9];
    const float* nw1 = (const float*)d_in[10];
    const float* nb1 = (const float*)d_in[11];
    const float* nw2 = (const float*)d_in[12];
    const float* nb2 = (const float*)d_in[13];
    const float* gw1 = (const float*)d_in[14];
    const float* gb1 = (const float*)d_in[15];
    const float* gw2 = (const float*)d_in[16];
    const float* gb2 = (const float*)d_in[17];
    float* out = (float*)d_out;

    const int SMF = 5*IMG + (24*132 + 32*132 + 24*132 + 512)*4;  // 218368
    cudaFuncSetAttribute(k_fused, cudaFuncAttributeMaxDynamicSharedMemorySize, SMF);

    k_init <<<5, 128>>>(nlw, ew1, ew2, nw1, nw2);
    k_fused<<<Mmol, NT, SMF>>>(charges, coords, emb, eb1, eb2, nb1, nb2,
                               gw1, gb1, gw2, gb2, out);
}